// round 6
// baseline (speedup 1.0000x reference)
#include <cuda_runtime.h>

typedef unsigned long long ull;

// Problem constants
#define BB  8
#define SS  1024
#define DD  1024
#define HH  16
#define DKK 64

// Scratch (allocation-free rule: __device__ globals)
__device__ float g_q[BB * HH * SS * DKK];
__device__ float g_k[BB * HH * SS * DKK];
__device__ float g_v[BB * HH * SS * DKK];
__device__ float g_ctx[BB * SS * DD];

// ---------------------------------------------------------------------------
// f32x2 packed helpers (Blackwell FFMA2 path — only reachable via PTX)
// ---------------------------------------------------------------------------
__device__ __forceinline__ ull ffma2(ull a, ull b, ull c) {
    ull d;
    asm("fma.rn.f32x2 %0, %1, %2, %3;" : "=l"(d) : "l"(a), "l"(b), "l"(c));
    return d;
}
__device__ __forceinline__ ull pack2(float lo, float hi) {
    ull d;
    asm("mov.b64 %0, {%1, %2};" : "=l"(d) : "f"(lo), "f"(hi));
    return d;
}
__device__ __forceinline__ void unpack2(ull v, float& lo, float& hi) {
    asm("mov.b64 {%0, %1}, %2;" : "=f"(lo), "=f"(hi) : "l"(v));
}

// ---------------------------------------------------------------------------
// Projection GEMM: C = X[M,K] @ W[N,K]^T + bias, scatter to [B,H,S,DK]
// 128x128 tile, BK=8, 256 threads, per-thread 8(m) x 4(n-pair) f32x2 accum
// ---------------------------------------------------------------------------
#define PBM 128
#define PBN 128
#define PBK 8
#define PST 132

__global__ __launch_bounds__(256, 2) void proj_kernel(const float* __restrict__ X,
                                                      const float* __restrict__ W,
                                                      const float* __restrict__ bias,
                                                      float* __restrict__ out) {
    __shared__ float As[PBK][PST];
    __shared__ float Bs[PBK][PST];
    const int tid = threadIdx.x;
    const int m0 = blockIdx.y * PBM, n0 = blockIdx.x * PBN;
    const int lr = tid >> 1;           // 0..127 row
    const int lc = (tid & 1) * 4;      // k 0 or 4
    const int tx = tid & 15, ty = tid >> 4;

    ull acc[8][4];
#pragma unroll
    for (int i = 0; i < 8; ++i)
#pragma unroll
        for (int j = 0; j < 4; ++j) acc[i][j] = 0ull;

    const float* Xp = X + (size_t)(m0 + lr) * DD + lc;
    const float* Wp = W + (size_t)(n0 + lr) * DD + lc;

    for (int kt = 0; kt < DD; kt += PBK) {
        float4 a = *(const float4*)(Xp + kt);
        float4 b = *(const float4*)(Wp + kt);
        __syncthreads();
        As[lc + 0][lr] = a.x; As[lc + 1][lr] = a.y;
        As[lc + 2][lr] = a.z; As[lc + 3][lr] = a.w;
        Bs[lc + 0][lr] = b.x; Bs[lc + 1][lr] = b.y;
        Bs[lc + 2][lr] = b.z; Bs[lc + 3][lr] = b.w;
        __syncthreads();
#pragma unroll
        for (int kk = 0; kk < PBK; ++kk) {
            float4 a1 = *(const float4*)&As[kk][ty * 8];
            float4 a2 = *(const float4*)&As[kk][ty * 8 + 4];
            ull av[8];
            av[0] = pack2(a1.x, a1.x); av[1] = pack2(a1.y, a1.y);
            av[2] = pack2(a1.z, a1.z); av[3] = pack2(a1.w, a1.w);
            av[4] = pack2(a2.x, a2.x); av[5] = pack2(a2.y, a2.y);
            av[6] = pack2(a2.z, a2.z); av[7] = pack2(a2.w, a2.w);
            ull bv[4];
#pragma unroll
            for (int j = 0; j < 4; ++j)
                bv[j] = *(const ull*)&Bs[kk][tx * 2 + 32 * j];
#pragma unroll
            for (int i = 0; i < 8; ++i)
#pragma unroll
                for (int j = 0; j < 4; ++j)
                    acc[i][j] = ffma2(av[i], bv[j], acc[i][j]);
        }
    }

#pragma unroll
    for (int i = 0; i < 8; ++i) {
        const int m = m0 + ty * 8 + i;
        const int bI = m >> 10, s = m & 1023;
#pragma unroll
        for (int j = 0; j < 4; ++j) {
            const int n = n0 + tx * 2 + 32 * j;
            float v0, v1;
            unpack2(acc[i][j], v0, v1);
            v0 += bias[n]; v1 += bias[n + 1];
            const int h = n >> 6, d = n & 63;
            float2 val; val.x = v0; val.y = v1;
            *(float2*)&out[((size_t)(bI * HH + h) * SS + s) * DKK + d] = val;
        }
    }
}

// ---------------------------------------------------------------------------
// Out-projection: out[m,n] = ctx @ Wo^T + bo + Qres
// ---------------------------------------------------------------------------
__global__ __launch_bounds__(256, 2) void outproj_kernel(const float* __restrict__ Xc,
                                                         const float* __restrict__ W,
                                                         const float* __restrict__ bias,
                                                         const float* __restrict__ Qres,
                                                         float* __restrict__ out) {
    __shared__ float As[PBK][PST];
    __shared__ float Bs[PBK][PST];
    const int tid = threadIdx.x;
    const int m0 = blockIdx.y * PBM, n0 = blockIdx.x * PBN;
    const int lr = tid >> 1;
    const int lc = (tid & 1) * 4;
    const int tx = tid & 15, ty = tid >> 4;

    ull acc[8][4];
#pragma unroll
    for (int i = 0; i < 8; ++i)
#pragma unroll
        for (int j = 0; j < 4; ++j) acc[i][j] = 0ull;

    const float* Xp = Xc + (size_t)(m0 + lr) * DD + lc;
    const float* Wp = W + (size_t)(n0 + lr) * DD + lc;

    for (int kt = 0; kt < DD; kt += PBK) {
        float4 a = *(const float4*)(Xp + kt);
        float4 b = *(const float4*)(Wp + kt);
        __syncthreads();
        As[lc + 0][lr] = a.x; As[lc + 1][lr] = a.y;
        As[lc + 2][lr] = a.z; As[lc + 3][lr] = a.w;
        Bs[lc + 0][lr] = b.x; Bs[lc + 1][lr] = b.y;
        Bs[lc + 2][lr] = b.z; Bs[lc + 3][lr] = b.w;
        __syncthreads();
#pragma unroll
        for (int kk = 0; kk < PBK; ++kk) {
            float4 a1 = *(const float4*)&As[kk][ty * 8];
            float4 a2 = *(const float4*)&As[kk][ty * 8 + 4];
            ull av[8];
            av[0] = pack2(a1.x, a1.x); av[1] = pack2(a1.y, a1.y);
            av[2] = pack2(a1.z, a1.z); av[3] = pack2(a1.w, a1.w);
            av[4] = pack2(a2.x, a2.x); av[5] = pack2(a2.y, a2.y);
            av[6] = pack2(a2.z, a2.z); av[7] = pack2(a2.w, a2.w);
            ull bv[4];
#pragma unroll
            for (int j = 0; j < 4; ++j)
                bv[j] = *(const ull*)&Bs[kk][tx * 2 + 32 * j];
#pragma unroll
            for (int i = 0; i < 8; ++i)
#pragma unroll
                for (int j = 0; j < 4; ++j)
                    acc[i][j] = ffma2(av[i], bv[j], acc[i][j]);
        }
    }

#pragma unroll
    for (int i = 0; i < 8; ++i) {
        const size_t m = m0 + ty * 8 + i;
#pragma unroll
        for (int j = 0; j < 4; ++j) {
            const int n = n0 + tx * 2 + 32 * j;
            float v0, v1;
            unpack2(acc[i][j], v0, v1);
            float2 qv = *(const float2*)&Qres[m * DD + n];
            float2 val;
            val.x = v0 + bias[n]     + qv.x;
            val.y = v1 + bias[n + 1] + qv.y;
            *(float2*)&out[m * DD + n] = val;
        }
    }
}

// ---------------------------------------------------------------------------
// Fused attention middle: scores (+mask, write) -> softmax (write attn) -> attn@V
// One CTA = 32 query rows of one (b,h). Full 32x1024 score panel lives in smem.
// Dynamic smem: S[32][1024] | Qs[64][36] (transposed) | KV (Kt[64][136] / Vt[128][64])
// ---------------------------------------------------------------------------
#define RM 32
#define KTS 136   // Kt stride
#define QTS 36    // Qs stride
#define SMEM_S_F   (RM * SS)                 // 32768 floats
#define SMEM_QS_F  (64 * QTS)                // 2304
#define SMEM_KV_F  (64 * KTS)                // 8704  (>= 128*64)
#define SMEM_TOT_B ((SMEM_S_F + SMEM_QS_F + SMEM_KV_F) * 4)

__global__ __launch_bounds__(256) void attn_fused_kernel(const float* __restrict__ q,
                                                         const float* __restrict__ k,
                                                         const float* __restrict__ v,
                                                         const unsigned char* __restrict__ mask,
                                                         float* __restrict__ scores,
                                                         float* __restrict__ attn,
                                                         float* __restrict__ ctx) {
    extern __shared__ float sm[];
    float* S  = sm;                       // [32][1024]
    float* Qs = sm + SMEM_S_F;            // [64][36]  Qs[d][m]
    float* KV = Qs + SMEM_QS_F;           // Kt[d][n] (pad 136) or Vt[n][d]

    const int bh = blockIdx.y;
    const int bI = bh >> 4, h = bh & 15;
    const int m0 = blockIdx.x * RM;
    const float* Qp = q + ((size_t)bh * SS + m0) * DKK;
    const float* Kp = k + (size_t)bh * SS * DKK;
    const float* Vp = v + (size_t)bh * SS * DKK;
    const unsigned char* Mp = mask + ((size_t)bI * SS + m0) * SS;
    float* Srow = scores + ((size_t)bh * SS + m0) * SS;
    float* Arow = attn   + ((size_t)bh * SS + m0) * SS;
    const int tid = threadIdx.x;

    // ---- load Q tile transposed: Qs[d][m] ----
    {
        const int r = tid >> 3;            // 0..31 (m)
        const int c = (tid & 7) * 8;       // d base
        float4 a0 = *(const float4*)&Qp[(size_t)r * DKK + c];
        float4 a1 = *(const float4*)&Qp[(size_t)r * DKK + c + 4];
        Qs[(c + 0) * QTS + r] = a0.x; Qs[(c + 1) * QTS + r] = a0.y;
        Qs[(c + 2) * QTS + r] = a0.z; Qs[(c + 3) * QTS + r] = a0.w;
        Qs[(c + 4) * QTS + r] = a1.x; Qs[(c + 5) * QTS + r] = a1.y;
        Qs[(c + 6) * QTS + r] = a1.z; Qs[(c + 7) * QTS + r] = a1.w;
    }

    // ---- Phase 1: scores = QK^T/8, mask, write scores gmem + S smem ----
    const int tx = tid & 15;               // n sub-lane
    const int ty = tid >> 4;               // m-pair: rows 2ty, 2ty+1
    for (int nt = 0; nt < 8; ++nt) {
        const int n0 = nt * 128;
        __syncthreads();                   // Qs ready (1st iter) / Kt free (later)
        // load K tile transposed: Kt[d][n], n = n0..n0+127
        {
            const int r  = tid >> 1;            // 0..127 (n)
            const int cb = (tid & 1) * 32;      // d base
            const float* kp = &Kp[(size_t)(n0 + r) * DKK + cb];
#pragma unroll
            for (int j = 0; j < 8; ++j) {
                float4 x = *(const float4*)(kp + j * 4);
                const int d = cb + j * 4;
                KV[(d + 0) * KTS + r] = x.x; KV[(d + 1) * KTS + r] = x.y;
                KV[(d + 2) * KTS + r] = x.z; KV[(d + 3) * KTS + r] = x.w;
            }
        }
        __syncthreads();

        ull acc[2][4];
#pragma unroll
        for (int i = 0; i < 2; ++i)
#pragma unroll
            for (int j = 0; j < 4; ++j) acc[i][j] = 0ull;

#pragma unroll 8
        for (int d = 0; d < 64; ++d) {
            const float q0 = Qs[d * QTS + 2 * ty];
            const float q1 = Qs[d * QTS + 2 * ty + 1];
            ull av0 = pack2(q0, q0);
            ull av1 = pack2(q1, q1);
            const float* kr = &KV[d * KTS + tx * 2];
            ull bv0 = *(const ull*)(kr);
            ull bv1 = *(const ull*)(kr + 32);
            ull bv2 = *(const ull*)(kr + 64);
            ull bv3 = *(const ull*)(kr + 96);
            acc[0][0] = ffma2(av0, bv0, acc[0][0]);
            acc[0][1] = ffma2(av0, bv1, acc[0][1]);
            acc[0][2] = ffma2(av0, bv2, acc[0][2]);
            acc[0][3] = ffma2(av0, bv3, acc[0][3]);
            acc[1][0] = ffma2(av1, bv0, acc[1][0]);
            acc[1][1] = ffma2(av1, bv1, acc[1][1]);
            acc[1][2] = ffma2(av1, bv2, acc[1][2]);
            acc[1][3] = ffma2(av1, bv3, acc[1][3]);
        }

        // epilogue: scale + mask, write S + scores
#pragma unroll
        for (int i = 0; i < 2; ++i) {
            const int m = 2 * ty + i;
#pragma unroll
            for (int j = 0; j < 4; ++j) {
                const int n = n0 + tx * 2 + 32 * j;
                float v0, v1;
                unpack2(acc[i][j], v0, v1);
                v0 *= 0.125f; v1 *= 0.125f;
                uchar2 mk = *(const uchar2*)&Mp[(size_t)m * SS + n];
                if (mk.x) v0 = -1e9f;
                if (mk.y) v1 = -1e9f;
                float2 val; val.x = v0; val.y = v1;
                *(float2*)&S[m * SS + n] = val;
                *(float2*)&Srow[(size_t)m * SS + n] = val;
            }
        }
    }

    // ---- Phase 2: softmax rows in smem, write attn gmem, normalize S ----
    __syncthreads();
    {
        const int w = tid >> 5, lane = tid & 31;
#pragma unroll
        for (int r = 0; r < 4; ++r) {
            const int row = w * 4 + r;
            float4 x[8];
            float mx = -1e30f;
#pragma unroll
            for (int i = 0; i < 8; ++i) {
                x[i] = *(const float4*)&S[row * SS + (lane + 32 * i) * 4];
                mx = fmaxf(mx, fmaxf(fmaxf(x[i].x, x[i].y), fmaxf(x[i].z, x[i].w)));
            }
#pragma unroll
            for (int o = 16; o; o >>= 1) mx = fmaxf(mx, __shfl_xor_sync(0xffffffffu, mx, o));
            float s = 0.f;
#pragma unroll
            for (int i = 0; i < 8; ++i) {
                x[i].x = __expf(x[i].x - mx); x[i].y = __expf(x[i].y - mx);
                x[i].z = __expf(x[i].z - mx); x[i].w = __expf(x[i].w - mx);
                s += (x[i].x + x[i].y) + (x[i].z + x[i].w);
            }
#pragma unroll
            for (int o = 16; o; o >>= 1) s += __shfl_xor_sync(0xffffffffu, s, o);
            const float inv = 1.0f / s;
#pragma unroll
            for (int i = 0; i < 8; ++i) {
                x[i].x *= inv; x[i].y *= inv; x[i].z *= inv; x[i].w *= inv;
                *(float4*)&S[row * SS + (lane + 32 * i) * 4] = x[i];
                *(float4*)&Arow[(size_t)row * SS + (lane + 32 * i) * 4] = x[i];
            }
        }
    }

    // ---- Phase 3: ctx = attn @ V ----
    const int tx3 = tid & 7;               // d-quad pair base
    const int mr  = tid >> 3;              // 0..31 (m)
    ull cacc[4];
#pragma unroll
    for (int j = 0; j < 4; ++j) cacc[j] = 0ull;

    for (int nt = 0; nt < 8; ++nt) {
        __syncthreads();                   // S normalized / Vt free
        // flat copy of V rows n0..n0+127 (128x64 contiguous)
        {
            const float* vsrc = Vp + (size_t)(nt * 128) * DKK;
#pragma unroll
            for (int i = 0; i < 8; ++i)
                *(float4*)&KV[(tid + 256 * i) * 4] = *(const float4*)&vsrc[(tid + 256 * i) * 4];
        }
        __syncthreads();

        const float* srow = &S[mr * SS + nt * 128];
#pragma unroll 4
        for (int kk = 0; kk < 128; ++kk) {
            const float a = srow[kk];
            ull ap = pack2(a, a);
            const float* vr = &KV[kk * 64 + tx3 * 4];
            float4 b0 = *(const float4*)vr;
            float4 b1 = *(const float4*)(vr + 32);
            cacc[0] = ffma2(ap, pack2(b0.x, b0.y), cacc[0]);
            cacc[1] = ffma2(ap, pack2(b0.z, b0.w), cacc[1]);
            cacc[2] = ffma2(ap, pack2(b1.x, b1.y), cacc[2]);
            cacc[3] = ffma2(ap, pack2(b1.z, b1.w), cacc[3]);
        }
    }

    // epilogue: ctx[b][s][h][d]
    {
        float r0, r1, r2, r3, r4, r5, r6, r7;
        unpack2(cacc[0], r0, r1); unpack2(cacc[1], r2, r3);
        unpack2(cacc[2], r4, r5); unpack2(cacc[3], r6, r7);
        float* cp = &ctx[(((size_t)bI * SS + m0 + mr) * HH + h) * DKK + tx3 * 4];
        float4 o0; o0.x = r0; o0.y = r1; o0.z = r2; o0.w = r3;
        float4 o1; o1.x = r4; o1.y = r5; o1.z = r6; o1.w = r7;
        *(float4*)(cp)      = o0;
        *(float4*)(cp + 32) = o1;
    }
}

// ---------------------------------------------------------------------------
// launch
// ---------------------------------------------------------------------------
extern "C" void kernel_launch(void* const* d_in, const int* in_sizes, int n_in,
                              void* d_out, int out_size) {
    const float* Q  = (const float*)d_in[0];
    const float* K  = (const float*)d_in[1];
    const float* V  = (const float*)d_in[2];
    const unsigned char* mask = (const unsigned char*)d_in[3];
    const float* Wq = (const float*)d_in[4];
    const float* bq = (const float*)d_in[5];
    const float* Wk = (const float*)d_in[6];
    const float* bk = (const float*)d_in[7];
    const float* Wv = (const float*)d_in[8];
    const float* bv = (const float*)d_in[9];
    const float* Wo = (const float*)d_in[10];
    const float* bo = (const float*)d_in[11];

    float* out    = (float*)d_out;                      // [B,S,D]
    float* attn   = out + (size_t)BB * SS * DD;         // [B,H,S,S]
    float* scores = attn + (size_t)BB * HH * SS * SS;   // [B,H,S,S]

    float *gq, *gk, *gv, *gctx;
    cudaGetSymbolAddress((void**)&gq, g_q);
    cudaGetSymbolAddress((void**)&gk, g_k);
    cudaGetSymbolAddress((void**)&gv, g_v);
    cudaGetSymbolAddress((void**)&gctx, g_ctx);

    static int smem_set = 0;
    if (!smem_set) {
        cudaFuncSetAttribute(attn_fused_kernel,
                             cudaFuncAttributeMaxDynamicSharedMemorySize, SMEM_TOT_B);
        smem_set = 1;
    }

    const dim3 projGrid(DD / PBN, (BB * SS) / PBM);     // (8,64)
    proj_kernel<<<projGrid, 256>>>(Q, Wq, bq, gq);
    proj_kernel<<<projGrid, 256>>>(K, Wk, bk, gk);
    proj_kernel<<<projGrid, 256>>>(V, Wv, bv, gv);

    const dim3 attnGrid(SS / RM, BB * HH);              // (32,128)
    attn_fused_kernel<<<attnGrid, 256, SMEM_TOT_B>>>(gq, gk, gv, mask, scores, attn, gctx);

    outproj_kernel<<<projGrid, 256>>>(gctx, Wo, bo, Q, out);
}

// round 7
// speedup vs baseline: 1.4456x; 1.4456x over previous
#include <cuda_runtime.h>

typedef unsigned long long ull;

// Problem constants
#define BB  8
#define SS  1024
#define DD  1024
#define HH  16
#define DKK 64

// Scratch (allocation-free rule: __device__ globals)
__device__ float g_q[BB * HH * SS * DKK];
__device__ float g_k[BB * HH * SS * DKK];
__device__ float g_v[BB * HH * SS * DKK];
__device__ float g_ctx[BB * SS * DD];

// ---------------------------------------------------------------------------
// f32x2 packed helpers (Blackwell FFMA2 path — only reachable via PTX)
// ---------------------------------------------------------------------------
__device__ __forceinline__ ull ffma2(ull a, ull b, ull c) {
    ull d;
    asm("fma.rn.f32x2 %0, %1, %2, %3;" : "=l"(d) : "l"(a), "l"(b), "l"(c));
    return d;
}
__device__ __forceinline__ ull pack2(float lo, float hi) {
    ull d;
    asm("mov.b64 %0, {%1, %2};" : "=l"(d) : "f"(lo), "f"(hi));
    return d;
}
__device__ __forceinline__ void unpack2(ull v, float& lo, float& hi) {
    asm("mov.b64 {%0, %1}, %2;" : "=f"(lo), "=f"(hi) : "l"(v));
}

// ---------------------------------------------------------------------------
// Projection GEMM: C = X[M,K] @ W[N,K]^T + bias, scatter to [B,H,S,DK]
// 128x128 tile, BK=8, 256 threads, per-thread 8(m) x 4(n-pair) f32x2 accum
// ---------------------------------------------------------------------------
#define PBM 128
#define PBN 128
#define PBK 8
#define PST 132

__global__ __launch_bounds__(256, 2) void proj_kernel(const float* __restrict__ X,
                                                      const float* __restrict__ W,
                                                      const float* __restrict__ bias,
                                                      float* __restrict__ out) {
    __shared__ float As[PBK][PST];
    __shared__ float Bs[PBK][PST];
    const int tid = threadIdx.x;
    const int m0 = blockIdx.y * PBM, n0 = blockIdx.x * PBN;
    const int lr = tid >> 1;           // 0..127 row
    const int lc = (tid & 1) * 4;      // k 0 or 4
    const int tx = tid & 15, ty = tid >> 4;

    ull acc[8][4];
#pragma unroll
    for (int i = 0; i < 8; ++i)
#pragma unroll
        for (int j = 0; j < 4; ++j) acc[i][j] = 0ull;

    const float* Xp = X + (size_t)(m0 + lr) * DD + lc;
    const float* Wp = W + (size_t)(n0 + lr) * DD + lc;

    for (int kt = 0; kt < DD; kt += PBK) {
        float4 a = *(const float4*)(Xp + kt);
        float4 b = *(const float4*)(Wp + kt);
        __syncthreads();
        As[lc + 0][lr] = a.x; As[lc + 1][lr] = a.y;
        As[lc + 2][lr] = a.z; As[lc + 3][lr] = a.w;
        Bs[lc + 0][lr] = b.x; Bs[lc + 1][lr] = b.y;
        Bs[lc + 2][lr] = b.z; Bs[lc + 3][lr] = b.w;
        __syncthreads();
#pragma unroll
        for (int kk = 0; kk < PBK; ++kk) {
            float4 a1 = *(const float4*)&As[kk][ty * 8];
            float4 a2 = *(const float4*)&As[kk][ty * 8 + 4];
            ull av[8];
            av[0] = pack2(a1.x, a1.x); av[1] = pack2(a1.y, a1.y);
            av[2] = pack2(a1.z, a1.z); av[3] = pack2(a1.w, a1.w);
            av[4] = pack2(a2.x, a2.x); av[5] = pack2(a2.y, a2.y);
            av[6] = pack2(a2.z, a2.z); av[7] = pack2(a2.w, a2.w);
            ull bv[4];
#pragma unroll
            for (int j = 0; j < 4; ++j)
                bv[j] = *(const ull*)&Bs[kk][tx * 2 + 32 * j];
#pragma unroll
            for (int i = 0; i < 8; ++i)
#pragma unroll
                for (int j = 0; j < 4; ++j)
                    acc[i][j] = ffma2(av[i], bv[j], acc[i][j]);
        }
    }

#pragma unroll
    for (int i = 0; i < 8; ++i) {
        const int m = m0 + ty * 8 + i;
        const int bI = m >> 10, s = m & 1023;
#pragma unroll
        for (int j = 0; j < 4; ++j) {
            const int n = n0 + tx * 2 + 32 * j;
            float v0, v1;
            unpack2(acc[i][j], v0, v1);
            v0 += bias[n]; v1 += bias[n + 1];
            const int h = n >> 6, d = n & 63;
            float2 val; val.x = v0; val.y = v1;
            *(float2*)&out[((size_t)(bI * HH + h) * SS + s) * DKK + d] = val;
        }
    }
}

// ---------------------------------------------------------------------------
// Out-projection: out[m,n] = ctx @ Wo^T + bo + Qres
// ---------------------------------------------------------------------------
__global__ __launch_bounds__(256, 2) void outproj_kernel(const float* __restrict__ Xc,
                                                         const float* __restrict__ W,
                                                         const float* __restrict__ bias,
                                                         const float* __restrict__ Qres,
                                                         float* __restrict__ out) {
    __shared__ float As[PBK][PST];
    __shared__ float Bs[PBK][PST];
    const int tid = threadIdx.x;
    const int m0 = blockIdx.y * PBM, n0 = blockIdx.x * PBN;
    const int lr = tid >> 1;
    const int lc = (tid & 1) * 4;
    const int tx = tid & 15, ty = tid >> 4;

    ull acc[8][4];
#pragma unroll
    for (int i = 0; i < 8; ++i)
#pragma unroll
        for (int j = 0; j < 4; ++j) acc[i][j] = 0ull;

    const float* Xp = Xc + (size_t)(m0 + lr) * DD + lc;
    const float* Wp = W + (size_t)(n0 + lr) * DD + lc;

    for (int kt = 0; kt < DD; kt += PBK) {
        float4 a = *(const float4*)(Xp + kt);
        float4 b = *(const float4*)(Wp + kt);
        __syncthreads();
        As[lc + 0][lr] = a.x; As[lc + 1][lr] = a.y;
        As[lc + 2][lr] = a.z; As[lc + 3][lr] = a.w;
        Bs[lc + 0][lr] = b.x; Bs[lc + 1][lr] = b.y;
        Bs[lc + 2][lr] = b.z; Bs[lc + 3][lr] = b.w;
        __syncthreads();
#pragma unroll
        for (int kk = 0; kk < PBK; ++kk) {
            float4 a1 = *(const float4*)&As[kk][ty * 8];
            float4 a2 = *(const float4*)&As[kk][ty * 8 + 4];
            ull av[8];
            av[0] = pack2(a1.x, a1.x); av[1] = pack2(a1.y, a1.y);
            av[2] = pack2(a1.z, a1.z); av[3] = pack2(a1.w, a1.w);
            av[4] = pack2(a2.x, a2.x); av[5] = pack2(a2.y, a2.y);
            av[6] = pack2(a2.z, a2.z); av[7] = pack2(a2.w, a2.w);
            ull bv[4];
#pragma unroll
            for (int j = 0; j < 4; ++j)
                bv[j] = *(const ull*)&Bs[kk][tx * 2 + 32 * j];
#pragma unroll
            for (int i = 0; i < 8; ++i)
#pragma unroll
                for (int j = 0; j < 4; ++j)
                    acc[i][j] = ffma2(av[i], bv[j], acc[i][j]);
        }
    }

#pragma unroll
    for (int i = 0; i < 8; ++i) {
        const size_t m = m0 + ty * 8 + i;
#pragma unroll
        for (int j = 0; j < 4; ++j) {
            const int n = n0 + tx * 2 + 32 * j;
            float v0, v1;
            unpack2(acc[i][j], v0, v1);
            float2 qv = *(const float2*)&Qres[m * DD + n];
            float2 val;
            val.x = v0 + bias[n]     + qv.x;
            val.y = v1 + bias[n + 1] + qv.y;
            *(float2*)&out[m * DD + n] = val;
        }
    }
}

// ---------------------------------------------------------------------------
// scores[bh,m,n] = (q[bh,m,:] . k[bh,n,:]) / 8, mask -> -1e9
// 128x128 tile, BK=32 (K=64 total), FFMA2, 256 threads, 2 CTAs/SM
// ---------------------------------------------------------------------------
#define SBK 32
#define SST 132

__global__ __launch_bounds__(256, 2) void scores_kernel(const float* __restrict__ q,
                                                        const float* __restrict__ k,
                                                        const unsigned char* __restrict__ mask,
                                                        float* __restrict__ scores) {
    __shared__ float As[SBK][SST];
    __shared__ float Bs[SBK][SST];
    const int bh = blockIdx.z;
    const int bI = bh >> 4;
    const float* A  = q + (size_t)bh * SS * DKK;
    const float* Bp = k + (size_t)bh * SS * DKK;

    const int tid = threadIdx.x;
    const int m0 = blockIdx.y * 128, n0 = blockIdx.x * 128;
    const int lr = tid >> 1;            // 0..127 row
    const int lc = (tid & 1) * 16;      // k base 0 or 16
    const int tx = tid & 15, ty = tid >> 4;

    ull acc[8][4];
#pragma unroll
    for (int i = 0; i < 8; ++i)
#pragma unroll
        for (int j = 0; j < 4; ++j) acc[i][j] = 0ull;

    const float* Ap = A  + (size_t)(m0 + lr) * DKK + lc;
    const float* Kp = Bp + (size_t)(n0 + lr) * DKK + lc;

#pragma unroll
    for (int kt = 0; kt < DKK; kt += SBK) {
        float4 a[4], b[4];
#pragma unroll
        for (int j = 0; j < 4; ++j) {
            a[j] = *(const float4*)(Ap + kt + j * 4);
            b[j] = *(const float4*)(Kp + kt + j * 4);
        }
        __syncthreads();
#pragma unroll
        for (int j = 0; j < 4; ++j) {
            const int kb = lc + j * 4;
            As[kb + 0][lr] = a[j].x; As[kb + 1][lr] = a[j].y;
            As[kb + 2][lr] = a[j].z; As[kb + 3][lr] = a[j].w;
            Bs[kb + 0][lr] = b[j].x; Bs[kb + 1][lr] = b[j].y;
            Bs[kb + 2][lr] = b[j].z; Bs[kb + 3][lr] = b[j].w;
        }
        __syncthreads();
#pragma unroll 8
        for (int kk = 0; kk < SBK; ++kk) {
            float4 a1 = *(const float4*)&As[kk][ty * 8];
            float4 a2 = *(const float4*)&As[kk][ty * 8 + 4];
            ull av[8];
            av[0] = pack2(a1.x, a1.x); av[1] = pack2(a1.y, a1.y);
            av[2] = pack2(a1.z, a1.z); av[3] = pack2(a1.w, a1.w);
            av[4] = pack2(a2.x, a2.x); av[5] = pack2(a2.y, a2.y);
            av[6] = pack2(a2.z, a2.z); av[7] = pack2(a2.w, a2.w);
            ull bv[4];
#pragma unroll
            for (int j = 0; j < 4; ++j)
                bv[j] = *(const ull*)&Bs[kk][tx * 2 + 32 * j];
#pragma unroll
            for (int i = 0; i < 8; ++i)
#pragma unroll
                for (int j = 0; j < 4; ++j)
                    acc[i][j] = ffma2(av[i], bv[j], acc[i][j]);
        }
    }

    float* srow = scores + (size_t)bh * SS * SS;
    const unsigned char* mrow = mask + (size_t)bI * SS * SS;
#pragma unroll
    for (int i = 0; i < 8; ++i) {
        const int m = m0 + ty * 8 + i;
#pragma unroll
        for (int j = 0; j < 4; ++j) {
            const int n = n0 + tx * 2 + 32 * j;
            float v0, v1;
            unpack2(acc[i][j], v0, v1);
            v0 *= 0.125f; v1 *= 0.125f;
            uchar2 mk = *(const uchar2*)&mrow[(size_t)m * SS + n];
            if (mk.x) v0 = -1e9f;
            if (mk.y) v1 = -1e9f;
            float2 val; val.x = v0; val.y = v1;
            *(float2*)&srow[(size_t)m * SS + n] = val;
        }
    }
}

// ---------------------------------------------------------------------------
// softmax over last dim (row length 1024), one block per row
// ---------------------------------------------------------------------------
__global__ __launch_bounds__(256) void softmax_kernel(const float* __restrict__ scores,
                                                      float* __restrict__ attn) {
    const size_t row = blockIdx.x;
    const float4* src = (const float4*)(scores + row * SS);
    const int t = threadIdx.x;
    float4 x = src[t];

    float m = fmaxf(fmaxf(x.x, x.y), fmaxf(x.z, x.w));
#pragma unroll
    for (int o = 16; o; o >>= 1) m = fmaxf(m, __shfl_xor_sync(0xffffffffu, m, o));

    __shared__ float smax[8];
    __shared__ float ssum[8];
    const int wid = t >> 5, lane = t & 31;
    if (lane == 0) smax[wid] = m;
    __syncthreads();
    float mx = smax[0];
#pragma unroll
    for (int i = 1; i < 8; ++i) mx = fmaxf(mx, smax[i]);

    float4 e;
    e.x = __expf(x.x - mx); e.y = __expf(x.y - mx);
    e.z = __expf(x.z - mx); e.w = __expf(x.w - mx);
    float s = e.x + e.y + e.z + e.w;
#pragma unroll
    for (int o = 16; o; o >>= 1) s += __shfl_xor_sync(0xffffffffu, s, o);
    if (lane == 0) ssum[wid] = s;
    __syncthreads();
    float tot = 0.f;
#pragma unroll
    for (int i = 0; i < 8; ++i) tot += ssum[i];

    const float inv = 1.0f / tot;
    float4 r = make_float4(e.x * inv, e.y * inv, e.z * inv, e.w * inv);
    ((float4*)(attn + row * SS))[t] = r;
}

// ---------------------------------------------------------------------------
// ctx[b,m,h,d] = sum_n attn[bh,m,n] * v[bh,n,d]   (A@B, K=1024, N=64)
// 128(m) x 64(n) tile, BK=32, FFMA2, per-thread 8(m) x 2(n-pair)
// ---------------------------------------------------------------------------
#define CBK 32
#define CST 132

__global__ __launch_bounds__(256, 2) void context_kernel(const float* __restrict__ attn,
                                                         const float* __restrict__ v,
                                                         float* __restrict__ ctx) {
    __shared__ float As[CBK][CST];
    __shared__ float Bs[CBK][64];
    const int bh = blockIdx.z;
    const int h = bh & 15, bI = bh >> 4;
    const float* A  = attn + (size_t)bh * SS * SS;
    const float* Bp = v + (size_t)bh * SS * DKK;

    const int tid = threadIdx.x;
    const int m0 = blockIdx.y * 128;
    const int lr = tid >> 1;            // 0..127 (m row)
    const int lc = (tid & 1) * 16;      // k base 0/16
    const int br = tid >> 3;            // 0..31  (k row for B)
    const int bc = (tid & 7) * 8;       // 0..56  (d base for B)
    const int tx = tid & 15, ty = tid >> 4;

    ull acc[8][2];
#pragma unroll
    for (int i = 0; i < 8; ++i) { acc[i][0] = 0ull; acc[i][1] = 0ull; }

    const float* Arp = A + (size_t)(m0 + lr) * SS + lc;

    for (int kt = 0; kt < SS; kt += CBK) {
        float4 a[4];
#pragma unroll
        for (int j = 0; j < 4; ++j)
            a[j] = *(const float4*)(Arp + kt + j * 4);
        float4 b0 = *(const float4*)&Bp[(size_t)(kt + br) * DKK + bc];
        float4 b1 = *(const float4*)&Bp[(size_t)(kt + br) * DKK + bc + 4];
        __syncthreads();
#pragma unroll
        for (int j = 0; j < 4; ++j) {
            const int kb = lc + j * 4;
            As[kb + 0][lr] = a[j].x; As[kb + 1][lr] = a[j].y;
            As[kb + 2][lr] = a[j].z; As[kb + 3][lr] = a[j].w;
        }
        *(float4*)&Bs[br][bc]     = b0;
        *(float4*)&Bs[br][bc + 4] = b1;
        __syncthreads();
#pragma unroll 8
        for (int kk = 0; kk < CBK; ++kk) {
            float4 a1 = *(const float4*)&As[kk][ty * 8];
            float4 a2 = *(const float4*)&As[kk][ty * 8 + 4];
            ull av[8];
            av[0] = pack2(a1.x, a1.x); av[1] = pack2(a1.y, a1.y);
            av[2] = pack2(a1.z, a1.z); av[3] = pack2(a1.w, a1.w);
            av[4] = pack2(a2.x, a2.x); av[5] = pack2(a2.y, a2.y);
            av[6] = pack2(a2.z, a2.z); av[7] = pack2(a2.w, a2.w);
            ull bv0 = *(const ull*)&Bs[kk][tx * 2];
            ull bv1 = *(const ull*)&Bs[kk][tx * 2 + 32];
#pragma unroll
            for (int i = 0; i < 8; ++i) {
                acc[i][0] = ffma2(av[i], bv0, acc[i][0]);
                acc[i][1] = ffma2(av[i], bv1, acc[i][1]);
            }
        }
    }

#pragma unroll
    for (int i = 0; i < 8; ++i) {
        const int m = m0 + ty * 8 + i;
        float* cp = &ctx[(((size_t)bI * SS + m) * HH + h) * DKK];
#pragma unroll
        for (int j = 0; j < 2; ++j) {
            const int d = tx * 2 + 32 * j;
            float v0, v1;
            unpack2(acc[i][j], v0, v1);
            float2 val; val.x = v0; val.y = v1;
            *(float2*)&cp[d] = val;
        }
    }
}

// ---------------------------------------------------------------------------
// launch
// ---------------------------------------------------------------------------
extern "C" void kernel_launch(void* const* d_in, const int* in_sizes, int n_in,
                              void* d_out, int out_size) {
    const float* Q  = (const float*)d_in[0];
    const float* K  = (const float*)d_in[1];
    const float* V  = (const float*)d_in[2];
    const unsigned char* mask = (const unsigned char*)d_in[3];
    const float* Wq = (const float*)d_in[4];
    const float* bq = (const float*)d_in[5];
    const float* Wk = (const float*)d_in[6];
    const float* bk = (const float*)d_in[7];
    const float* Wv = (const float*)d_in[8];
    const float* bv = (const float*)d_in[9];
    const float* Wo = (const float*)d_in[10];
    const float* bo = (const float*)d_in[11];

    float* out    = (float*)d_out;                      // [B,S,D]
    float* attn   = out + (size_t)BB * SS * DD;         // [B,H,S,S]
    float* scores = attn + (size_t)BB * HH * SS * SS;   // [B,H,S,S]

    float *gq, *gk, *gv, *gctx;
    cudaGetSymbolAddress((void**)&gq, g_q);
    cudaGetSymbolAddress((void**)&gk, g_k);
    cudaGetSymbolAddress((void**)&gv, g_v);
    cudaGetSymbolAddress((void**)&gctx, g_ctx);

    const dim3 projGrid(DD / PBN, (BB * SS) / PBM);     // (8,64)
    proj_kernel<<<projGrid, 256>>>(Q, Wq, bq, gq);
    proj_kernel<<<projGrid, 256>>>(K, Wk, bk, gk);
    proj_kernel<<<projGrid, 256>>>(V, Wv, bv, gv);

    const dim3 scoreGrid(SS / 128, SS / 128, BB * HH);  // (8,8,128)
    scores_kernel<<<scoreGrid, 256>>>(gq, gk, mask, scores);

    softmax_kernel<<<BB * HH * SS, 256>>>(scores, attn);

    const dim3 ctxGrid(1, SS / 128, BB * HH);           // (1,8,128)
    context_kernel<<<ctxGrid, 256>>>(attn, gv, gctx);

    outproj_kernel<<<projGrid, 256>>>(gctx, Wo, bo, Q, out);
}

// round 10
// speedup vs baseline: 2.5598x; 1.7707x over previous
#include <cuda_runtime.h>
#include <cuda_bf16.h>
#include <cstdint>

typedef unsigned int u32;

#define BB  8
#define SS  1024
#define DD  1024
#define HH  16
#define DKK 64
#define MTOT (BB * SS)          // 8192
#define NEL  (MTOT * DD)        // 8,388,608
#define WEL  (DD * DD)          // 1,048,576
#define AEL  (134217728ULL)     // B*H*S*S

// ---------------------------------------------------------------------------
// Scratch (__device__ globals; allocation-free rule)
// ---------------------------------------------------------------------------
__device__ __nv_bfloat16 gQih[NEL], gQil[NEL], gKih[NEL], gKil[NEL], gVih[NEL], gVil[NEL];
__device__ __nv_bfloat16 gWqh[WEL], gWql[WEL], gWkh[WEL], gWkl[WEL];
__device__ __nv_bfloat16 gWvh[WEL], gWvl[WEL], gWoh[WEL], gWol[WEL];
__device__ __nv_bfloat16 gqh[NEL], gql[NEL], gkh[NEL], gkl[NEL], gvh[NEL], gvl[NEL];
__device__ __nv_bfloat16 gattnh[AEL], gattnl[AEL];
__device__ __nv_bfloat16 gctxh[NEL], gctxl[NEL];

// ---------------------------------------------------------------------------
// Baseline-ISA tensor helpers (compile under compute_103: no 'a' features)
// ---------------------------------------------------------------------------
__device__ __forceinline__ u32 smem_u32(const void* p) {
    u32 a;
    asm("{ .reg .u64 t; cvta.to.shared.u64 t, %1; cvt.u32.u64 %0, t; }" : "=r"(a) : "l"(p));
    return a;
}
__device__ __forceinline__ void ldsm4(u32& r0, u32& r1, u32& r2, u32& r3, u32 a) {
    asm volatile("ldmatrix.sync.aligned.m8n8.x4.shared.b16 {%0,%1,%2,%3}, [%4];"
                 : "=r"(r0), "=r"(r1), "=r"(r2), "=r"(r3) : "r"(a));
}
__device__ __forceinline__ void ldsm4t(u32& r0, u32& r1, u32& r2, u32& r3, u32 a) {
    asm volatile("ldmatrix.sync.aligned.m8n8.x4.trans.shared.b16 {%0,%1,%2,%3}, [%4];"
                 : "=r"(r0), "=r"(r1), "=r"(r2), "=r"(r3) : "r"(a));
}
__device__ __forceinline__ void mma_bf16(float* c, const u32* a, u32 b0, u32 b1) {
    asm volatile(
        "mma.sync.aligned.m16n8k16.row.col.f32.bf16.bf16.f32 "
        "{%0,%1,%2,%3}, {%4,%5,%6,%7}, {%8,%9}, {%0,%1,%2,%3};"
        : "+f"(c[0]), "+f"(c[1]), "+f"(c[2]), "+f"(c[3])
        : "r"(a[0]), "r"(a[1]), "r"(a[2]), "r"(a[3]), "r"(b0), "r"(b1));
}
__device__ __forceinline__ void cp16(u32 dst, const void* src) {
    asm volatile("cp.async.cg.shared.global [%0], [%1], 16;" :: "r"(dst), "l"(src));
}
#define CP_COMMIT() asm volatile("cp.async.commit_group;" ::: "memory")
#define CP_WAIT0()  asm volatile("cp.async.wait_group 0;" ::: "memory")
#define CP_WAIT1()  asm volatile("cp.async.wait_group 1;" ::: "memory")

__device__ __forceinline__ void split1(float v, __nv_bfloat16& h, __nv_bfloat16& l) {
    h = __float2bfloat16(v);
    l = __float2bfloat16(v - __bfloat162float(h));
}

// ---------------------------------------------------------------------------
// Split fp32 -> (bf16 hi, bf16 lo)
// ---------------------------------------------------------------------------
__global__ __launch_bounds__(256) void split_kernel(const float* __restrict__ x,
                                                    __nv_bfloat16* __restrict__ hi,
                                                    __nv_bfloat16* __restrict__ lo,
                                                    int n) {
    const int i = (blockIdx.x * 256 + threadIdx.x) * 4;
    if (i >= n) return;
    float4 v = *(const float4*)(x + i);
    __nv_bfloat16 h0, h1, h2, h3, l0, l1, l2, l3;
    split1(v.x, h0, l0); split1(v.y, h1, l1);
    split1(v.z, h2, l2); split1(v.w, h3, l3);
    __nv_bfloat162 H0; H0.x = h0; H0.y = h1;
    __nv_bfloat162 H1; H1.x = h2; H1.y = h3;
    __nv_bfloat162 L0; L0.x = l0; L0.y = l1;
    __nv_bfloat162 L1; L1.x = l2; L1.y = l3;
    *(__nv_bfloat162*)(hi + i)     = H0;
    *(__nv_bfloat162*)(hi + i + 2) = H1;
    *(__nv_bfloat162*)(lo + i)     = L0;
    *(__nv_bfloat162*)(lo + i + 2) = L1;
}

// ---------------------------------------------------------------------------
// mma.sync GEMM: C[8192x1024] = A[M,K] @ B[N,K]^T (+bias [+Qres]), bf16x3
// 128x128 tile, BK=32, cp.async double-buffered, 8 warps (warp tile 64x32)
// MODE 0: bf16 hi/lo scattered to [B,H,S,DK]
// MODE 2: fp32 [M,N] + bias + Qres
// ---------------------------------------------------------------------------
#define GST    80                 // smem row stride bytes (40 bf16, conflict-free ldsm)
#define GMAT   (128 * GST)        // 10240
#define GSTAGE (4 * GMAT)         // 40960: [Ah][Al][Bh][Bl]
#define GEMM_SMEM (2 * GSTAGE)    // 81920

template <int MODE>
__global__ __launch_bounds__(256) void gemm_mma(
    const __nv_bfloat16* __restrict__ Ahg, const __nv_bfloat16* __restrict__ Alg,
    const __nv_bfloat16* __restrict__ Bhg, const __nv_bfloat16* __restrict__ Blg,
    const float* __restrict__ bias, const float* __restrict__ Qres,
    __nv_bfloat16* __restrict__ o_hi, __nv_bfloat16* __restrict__ o_lo,
    float* __restrict__ o_f) {
    extern __shared__ char smarr[];
    const u32 sb = smem_u32(smarr);
    const int tid = threadIdx.x, lane = tid & 31, wid = tid >> 5;
    const int wm = wid & 1, wn = wid >> 1;
    const int m0 = blockIdx.y * 128, n0 = blockIdx.x * 128;

    float acc[4][4][4];
#pragma unroll
    for (int a = 0; a < 4; ++a)
#pragma unroll
        for (int b = 0; b < 4; ++b)
#pragma unroll
            for (int c = 0; c < 4; ++c) acc[a][b][c] = 0.f;

    const __nv_bfloat16* gsrc[4] = {
        Ahg + (size_t)m0 * DD, Alg + (size_t)m0 * DD,
        Bhg + (size_t)n0 * DD, Blg + (size_t)n0 * DD};

    auto LOAD = [&](int kt, int buf) {
        const int ko = kt * 32;
#pragma unroll
        for (int mat = 0; mat < 4; ++mat)
#pragma unroll
            for (int i = 0; i < 2; ++i) {
                const int ch = tid + i * 256;
                const int row = ch >> 2, c = ch & 3;
                cp16(sb + buf * GSTAGE + mat * GMAT + row * GST + c * 16,
                     gsrc[mat] + (size_t)row * DD + ko + c * 8);
            }
    };

    auto COMP = [&](int buf) {
        const u32 st = sb + buf * GSTAGE;
#pragma unroll
        for (int s = 0; s < 2; ++s) {
            u32 ah[4][4], al[4][4];
#pragma unroll
            for (int mt = 0; mt < 4; ++mt) {
                const int row = wm * 64 + mt * 16 + (lane & 15);
                const int colb = (s * 16 + (lane >> 4) * 8) * 2;
                const u32 ad = st + row * GST + colb;
                ldsm4(ah[mt][0], ah[mt][1], ah[mt][2], ah[mt][3], ad);
                ldsm4(al[mt][0], al[mt][1], al[mt][2], al[mt][3], ad + GMAT);
            }
            u32 bh[2][4], bl[2][4];
#pragma unroll
            for (int bt = 0; bt < 2; ++bt) {
                const int row = wn * 32 + bt * 16 + ((lane >> 4) & 1) * 8 + (lane & 7);
                const int colb = (s * 16 + ((lane >> 3) & 1) * 8) * 2;
                const u32 bd = st + 2 * GMAT + row * GST + colb;
                ldsm4(bh[bt][0], bh[bt][1], bh[bt][2], bh[bt][3], bd);
                ldsm4(bl[bt][0], bl[bt][1], bl[bt][2], bl[bt][3], bd + GMAT);
            }
#pragma unroll
            for (int mt = 0; mt < 4; ++mt)
#pragma unroll
                for (int bt = 0; bt < 2; ++bt)
#pragma unroll
                    for (int j = 0; j < 2; ++j) {
                        float* c = acc[mt][bt * 2 + j];
                        mma_bf16(c, ah[mt], bh[bt][2 * j], bh[bt][2 * j + 1]);
                        mma_bf16(c, ah[mt], bl[bt][2 * j], bl[bt][2 * j + 1]);
                        mma_bf16(c, al[mt], bh[bt][2 * j], bh[bt][2 * j + 1]);
                    }
        }
    };

    LOAD(0, 0); CP_COMMIT();
    for (int kt = 0; kt < 32; ++kt) {
        const int buf = kt & 1;
        if (kt + 1 < 32) { LOAD(kt + 1, buf ^ 1); CP_COMMIT(); CP_WAIT1(); }
        else             { CP_WAIT0(); }
        __syncthreads();
        COMP(buf);
        __syncthreads();
    }

    // epilogue
    const int r0 = lane >> 2, cp = (lane & 3) * 2;
#pragma unroll
    for (int mt = 0; mt < 4; ++mt)
#pragma unroll
        for (int i = 0; i < 2; ++i) {
            const int m = m0 + wm * 64 + mt * 16 + r0 + i * 8;
#pragma unroll
            for (int nt = 0; nt < 4; ++nt) {
                const int n = n0 + wn * 32 + nt * 8 + cp;
                float v0 = acc[mt][nt][i * 2 + 0] + __ldg(&bias[n]);
                float v1 = acc[mt][nt][i * 2 + 1] + __ldg(&bias[n + 1]);
                if (MODE == 0) {
                    const int bI = m >> 10, s = m & 1023;
                    const int h = n >> 6, d = n & 63;
                    const size_t o = ((size_t)(bI * HH + h) * SS + s) * DKK + d;
                    __nv_bfloat16 h0, h1, l0, l1;
                    split1(v0, h0, l0); split1(v1, h1, l1);
                    __nv_bfloat162 hh; hh.x = h0; hh.y = h1;
                    __nv_bfloat162 ll; ll.x = l0; ll.y = l1;
                    *(__nv_bfloat162*)&o_hi[o] = hh;
                    *(__nv_bfloat162*)&o_lo[o] = ll;
                } else {
                    const size_t o = (size_t)m * DD + n;
                    float2 qv = *(const float2*)&Qres[o];
                    float2 val; val.x = v0 + qv.x; val.y = v1 + qv.y;
                    *(float2*)&o_f[o] = val;
                }
            }
        }
}

// ---------------------------------------------------------------------------
// scores via mma.sync: per (b,h) 128x128 tile, K=64 single stage, bf16x3
// ---------------------------------------------------------------------------
#define SSTR 144
#define SMAT (128 * SSTR)       // 18432
#define SC_SMEM (4 * SMAT)      // 73728

__global__ __launch_bounds__(256) void scores_mma(
    const __nv_bfloat16* __restrict__ qh, const __nv_bfloat16* __restrict__ ql,
    const __nv_bfloat16* __restrict__ kh, const __nv_bfloat16* __restrict__ kl,
    const unsigned char* __restrict__ mask, float* __restrict__ scores) {
    extern __shared__ char smarr[];
    const u32 sb = smem_u32(smarr);
    const int tid = threadIdx.x, lane = tid & 31, wid = tid >> 5;
    const int wm = wid & 1, wn = wid >> 1;
    const int bh = blockIdx.z;
    const int m0 = blockIdx.y * 128, n0 = blockIdx.x * 128;

    const __nv_bfloat16* gsrc[4] = {
        qh + ((size_t)bh * SS + m0) * DKK, ql + ((size_t)bh * SS + m0) * DKK,
        kh + ((size_t)bh * SS + n0) * DKK, kl + ((size_t)bh * SS + n0) * DKK};
#pragma unroll
    for (int mat = 0; mat < 4; ++mat)
#pragma unroll
        for (int i = 0; i < 4; ++i) {
            const int ch = tid + i * 256;
            const int row = ch >> 3, c = ch & 7;
            cp16(sb + mat * SMAT + row * SSTR + c * 16,
                 gsrc[mat] + (size_t)row * DKK + c * 8);
        }
    CP_COMMIT(); CP_WAIT0();
    __syncthreads();

    float acc[4][4][4];
#pragma unroll
    for (int a = 0; a < 4; ++a)
#pragma unroll
        for (int b = 0; b < 4; ++b)
#pragma unroll
            for (int c = 0; c < 4; ++c) acc[a][b][c] = 0.f;

#pragma unroll
    for (int s = 0; s < 4; ++s) {
        u32 ah[4][4], al[4][4];
#pragma unroll
        for (int mt = 0; mt < 4; ++mt) {
            const int row = wm * 64 + mt * 16 + (lane & 15);
            const int colb = (s * 16 + (lane >> 4) * 8) * 2;
            const u32 ad = sb + row * SSTR + colb;
            ldsm4(ah[mt][0], ah[mt][1], ah[mt][2], ah[mt][3], ad);
            ldsm4(al[mt][0], al[mt][1], al[mt][2], al[mt][3], ad + SMAT);
        }
        u32 bh_[2][4], bl_[2][4];
#pragma unroll
        for (int bt = 0; bt < 2; ++bt) {
            const int row = wn * 32 + bt * 16 + ((lane >> 4) & 1) * 8 + (lane & 7);
            const int colb = (s * 16 + ((lane >> 3) & 1) * 8) * 2;
            const u32 bd = sb + 2 * SMAT + row * SSTR + colb;
            ldsm4(bh_[bt][0], bh_[bt][1], bh_[bt][2], bh_[bt][3], bd);
            ldsm4(bl_[bt][0], bl_[bt][1], bl_[bt][2], bl_[bt][3], bd + SMAT);
        }
#pragma unroll
        for (int mt = 0; mt < 4; ++mt)
#pragma unroll
            for (int bt = 0; bt < 2; ++bt)
#pragma unroll
                for (int j = 0; j < 2; ++j) {
                    float* c = acc[mt][bt * 2 + j];
                    mma_bf16(c, ah[mt], bh_[bt][2 * j], bh_[bt][2 * j + 1]);
                    mma_bf16(c, ah[mt], bl_[bt][2 * j], bl_[bt][2 * j + 1]);
                    mma_bf16(c, al[mt], bh_[bt][2 * j], bh_[bt][2 * j + 1]);
                }
    }

    const int bI = bh >> 4;
    float* srow = scores + (size_t)bh * SS * SS;
    const unsigned char* mrow = mask + (size_t)bI * SS * SS;
    const int r0 = lane >> 2, cp = (lane & 3) * 2;
#pragma unroll
    for (int mt = 0; mt < 4; ++mt)
#pragma unroll
        for (int i = 0; i < 2; ++i) {
            const int m = m0 + wm * 64 + mt * 16 + r0 + i * 8;
#pragma unroll
            for (int nt = 0; nt < 4; ++nt) {
                const int n = n0 + wn * 32 + nt * 8 + cp;
                float v0 = acc[mt][nt][i * 2 + 0] * 0.125f;
                float v1 = acc[mt][nt][i * 2 + 1] * 0.125f;
                uchar2 mk = *(const uchar2*)&mrow[(size_t)m * SS + n];
                if (mk.x) v0 = -1e9f;
                if (mk.y) v1 = -1e9f;
                float2 val; val.x = v0; val.y = v1;
                *(float2*)&srow[(size_t)m * SS + n] = val;
            }
        }
}

// ---------------------------------------------------------------------------
// softmax (row length 1024) — writes fp32 attn + bf16 hi/lo splits
// ---------------------------------------------------------------------------
__global__ __launch_bounds__(256) void softmax_kernel(const float* __restrict__ scores,
                                                      float* __restrict__ attn,
                                                      __nv_bfloat16* __restrict__ ahi,
                                                      __nv_bfloat16* __restrict__ alo) {
    const size_t row = blockIdx.x;
    const float4* src = (const float4*)(scores + row * SS);
    const int t = threadIdx.x;
    float4 x = src[t];

    float m = fmaxf(fmaxf(x.x, x.y), fmaxf(x.z, x.w));
#pragma unroll
    for (int o = 16; o; o >>= 1) m = fmaxf(m, __shfl_xor_sync(0xffffffffu, m, o));

    __shared__ float smax[8];
    __shared__ float ssum[8];
    const int wid = t >> 5, lane = t & 31;
    if (lane == 0) smax[wid] = m;
    __syncthreads();
    float mx = smax[0];
#pragma unroll
    for (int i = 1; i < 8; ++i) mx = fmaxf(mx, smax[i]);

    float4 e;
    e.x = __expf(x.x - mx); e.y = __expf(x.y - mx);
    e.z = __expf(x.z - mx); e.w = __expf(x.w - mx);
    float s = e.x + e.y + e.z + e.w;
#pragma unroll
    for (int o = 16; o; o >>= 1) s += __shfl_xor_sync(0xffffffffu, s, o);
    if (lane == 0) ssum[wid] = s;
    __syncthreads();
    float tot = 0.f;
#pragma unroll
    for (int i = 0; i < 8; ++i) tot += ssum[i];

    const float inv = 1.0f / tot;
    float4 r = make_float4(e.x * inv, e.y * inv, e.z * inv, e.w * inv);
    ((float4*)(attn + row * SS))[t] = r;

    __nv_bfloat16 h0, h1, h2, h3, l0, l1, l2, l3;
    split1(r.x, h0, l0); split1(r.y, h1, l1);
    split1(r.z, h2, l2); split1(r.w, h3, l3);
    __nv_bfloat162 H0; H0.x = h0; H0.y = h1;
    __nv_bfloat162 H1; H1.x = h2; H1.y = h3;
    __nv_bfloat162 L0; L0.x = l0; L0.y = l1;
    __nv_bfloat162 L1; L1.x = l2; L1.y = l3;
    const size_t o = row * SS + t * 4;
    *(__nv_bfloat162*)(ahi + o)     = H0;
    *(__nv_bfloat162*)(ahi + o + 2) = H1;
    *(__nv_bfloat162*)(alo + o)     = L0;
    *(__nv_bfloat162*)(alo + o + 2) = L1;
}

// ---------------------------------------------------------------------------
// context via mma.sync: per (b,h) ctx[1024x64] = attn[1024x1024] @ V[1024x64]
// CTA tile 128(m) x 64(n), BK=32, double-buffered; V operand via ldmatrix.trans
// ---------------------------------------------------------------------------
#define CAMAT  (128 * 80)                 // 10240 (attn 128x32 bf16, stride 80B)
#define CVMAT  (32 * 144)                 // 4608  (V 32x64 bf16, stride 144B)
#define CSTAGE (2 * CAMAT + 2 * CVMAT)    // 29696: [Ah][Al][Vh][Vl]
#define CTX_SMEM (2 * CSTAGE)             // 59392

__global__ __launch_bounds__(256) void context_mma(
    const __nv_bfloat16* __restrict__ ahg, const __nv_bfloat16* __restrict__ alg,
    const __nv_bfloat16* __restrict__ vhg, const __nv_bfloat16* __restrict__ vlg,
    __nv_bfloat16* __restrict__ ctxh, __nv_bfloat16* __restrict__ ctxl) {
    extern __shared__ char smarr[];
    const u32 sb = smem_u32(smarr);
    const int tid = threadIdx.x, lane = tid & 31, wid = tid >> 5;
    const int wm = wid >> 1, wn = wid & 1;
    const int bh = blockIdx.y;
    const int m0 = blockIdx.x * 128;

    const __nv_bfloat16* asrc[2] = {ahg + ((size_t)bh * SS + m0) * SS,
                                    alg + ((size_t)bh * SS + m0) * SS};
    const __nv_bfloat16* vsrc[2] = {vhg + (size_t)bh * SS * DKK,
                                    vlg + (size_t)bh * SS * DKK};

    float acc[2][4][4];
#pragma unroll
    for (int a = 0; a < 2; ++a)
#pragma unroll
        for (int b = 0; b < 4; ++b)
#pragma unroll
            for (int c = 0; c < 4; ++c) acc[a][b][c] = 0.f;

    auto LOAD = [&](int kt, int buf) {
        const int ko = kt * 32;
#pragma unroll
        for (int half = 0; half < 2; ++half) {
#pragma unroll
            for (int i = 0; i < 2; ++i) {
                const int ch = tid + i * 256;
                const int row = ch >> 2, c = ch & 3;
                cp16(sb + buf * CSTAGE + half * CAMAT + row * 80 + c * 16,
                     asrc[half] + (size_t)row * SS + ko + c * 8);
            }
            const int vr = tid >> 3, vc = tid & 7;
            cp16(sb + buf * CSTAGE + 2 * CAMAT + half * CVMAT + vr * 144 + vc * 16,
                 vsrc[half] + (size_t)(ko + vr) * DKK + vc * 8);
        }
    };

    auto COMP = [&](int buf) {
        const u32 st = sb + buf * CSTAGE;
#pragma unroll
        for (int s = 0; s < 2; ++s) {
            u32 ah[2][4], al[2][4];
#pragma unroll
            for (int mt = 0; mt < 2; ++mt) {
                const int row = wm * 32 + mt * 16 + (lane & 15);
                const int colb = (s * 16 + (lane >> 4) * 8) * 2;
                const u32 ad = st + row * 80 + colb;
                ldsm4(ah[mt][0], ah[mt][1], ah[mt][2], ah[mt][3], ad);
                ldsm4(al[mt][0], al[mt][1], al[mt][2], al[mt][3], ad + CAMAT);
            }
            u32 bh_[2][4], bl_[2][4];
#pragma unroll
            for (int bt = 0; bt < 2; ++bt) {
                const int rowk = s * 16 + (lane & 7) + ((lane >> 3) & 1) * 8;
                const int coln = wn * 32 + bt * 16 + ((lane >> 4) & 1) * 8;
                const u32 bd = st + 2 * CAMAT + rowk * 144 + coln * 2;
                ldsm4t(bh_[bt][0], bh_[bt][1], bh_[bt][2], bh_[bt][3], bd);
                ldsm4t(bl_[bt][0], bl_[bt][1], bl_[bt][2], bl_[bt][3], bd + CVMAT);
            }
#pragma unroll
            for (int mt = 0; mt < 2; ++mt)
#pragma unroll
                for (int bt = 0; bt < 2; ++bt)
#pragma unroll
                    for (int j = 0; j < 2; ++j) {
                        float* c = acc[mt][bt * 2 + j];
                        mma_bf16(c, ah[mt], bh_[bt][2 * j], bh_[bt][2 * j + 1]);
                        mma_bf16(c, ah[mt], bl_[bt][2 * j], bl_[bt][2 * j + 1]);
                        mma_bf16(c, al[mt], bh_[bt][2 * j], bh_[bt][2 * j + 1]);
                    }
        }
    };

    LOAD(0, 0); CP_COMMIT();
    for (int kt = 0; kt < 32; ++kt) {
        const int buf = kt & 1;
        if (kt + 1 < 32) { LOAD(kt + 1, buf ^ 1); CP_COMMIT(); CP_WAIT1(); }
        else             { CP_WAIT0(); }
        __syncthreads();
        COMP(buf);
        __syncthreads();
    }

    const int bI = bh >> 4, h = bh & 15;
    const int r0 = lane >> 2, cp = (lane & 3) * 2;
#pragma unroll
    for (int mt = 0; mt < 2; ++mt)
#pragma unroll
        for (int i = 0; i < 2; ++i) {
            const int m = m0 + wm * 32 + mt * 16 + r0 + i * 8;
#pragma unroll
            for (int nt = 0; nt < 4; ++nt) {
                const int n = wn * 32 + nt * 8 + cp;
                float v0 = acc[mt][nt][i * 2 + 0];
                float v1 = acc[mt][nt][i * 2 + 1];
                __nv_bfloat16 h0, h1, l0, l1;
                split1(v0, h0, l0); split1(v1, h1, l1);
                __nv_bfloat162 hh; hh.x = h0; hh.y = h1;
                __nv_bfloat162 ll; ll.x = l0; ll.y = l1;
                const size_t o = ((size_t)bI * SS + m) * DD + h * DKK + n;
                *(__nv_bfloat162*)&ctxh[o] = hh;
                *(__nv_bfloat162*)&ctxl[o] = ll;
            }
        }
}

// ---------------------------------------------------------------------------
// launch
// ---------------------------------------------------------------------------
extern "C" void kernel_launch(void* const* d_in, const int* in_sizes, int n_in,
                              void* d_out, int out_size) {
    const float* Q  = (const float*)d_in[0];
    const float* K  = (const float*)d_in[1];
    const float* V  = (const float*)d_in[2];
    const unsigned char* mask = (const unsigned char*)d_in[3];
    const float* Wq = (const float*)d_in[4];
    const float* bq = (const float*)d_in[5];
    const float* Wk = (const float*)d_in[6];
    const float* bk = (const float*)d_in[7];
    const float* Wv = (const float*)d_in[8];
    const float* bv = (const float*)d_in[9];
    const float* Wo = (const float*)d_in[10];
    const float* bo = (const float*)d_in[11];

    float* out    = (float*)d_out;
    float* attn   = out + (size_t)BB * SS * DD;
    float* scores = attn + (size_t)BB * HH * SS * SS;

    __nv_bfloat16 *pQih, *pQil, *pKih, *pKil, *pVih, *pVil;
    __nv_bfloat16 *pWqh, *pWql, *pWkh, *pWkl, *pWvh, *pWvl, *pWoh, *pWol;
    __nv_bfloat16 *pqh, *pql, *pkh, *pkl, *pvh, *pvl, *pah, *pal, *pctxh, *pctxl;
    cudaGetSymbolAddress((void**)&pQih, gQih); cudaGetSymbolAddress((void**)&pQil, gQil);
    cudaGetSymbolAddress((void**)&pKih, gKih); cudaGetSymbolAddress((void**)&pKil, gKil);
    cudaGetSymbolAddress((void**)&pVih, gVih); cudaGetSymbolAddress((void**)&pVil, gVil);
    cudaGetSymbolAddress((void**)&pWqh, gWqh); cudaGetSymbolAddress((void**)&pWql, gWql);
    cudaGetSymbolAddress((void**)&pWkh, gWkh); cudaGetSymbolAddress((void**)&pWkl, gWkl);
    cudaGetSymbolAddress((void**)&pWvh, gWvh); cudaGetSymbolAddress((void**)&pWvl, gWvl);
    cudaGetSymbolAddress((void**)&pWoh, gWoh); cudaGetSymbolAddress((void**)&pWol, gWol);
    cudaGetSymbolAddress((void**)&pqh, gqh);   cudaGetSymbolAddress((void**)&pql, gql);
    cudaGetSymbolAddress((void**)&pkh, gkh);   cudaGetSymbolAddress((void**)&pkl, gkl);
    cudaGetSymbolAddress((void**)&pvh, gvh);   cudaGetSymbolAddress((void**)&pvl, gvl);
    cudaGetSymbolAddress((void**)&pah, gattnh); cudaGetSymbolAddress((void**)&pal, gattnl);
    cudaGetSymbolAddress((void**)&pctxh, gctxh); cudaGetSymbolAddress((void**)&pctxl, gctxl);

    static int initd = 0;
    if (!initd) {
        cudaFuncSetAttribute(gemm_mma<0>, cudaFuncAttributeMaxDynamicSharedMemorySize, GEMM_SMEM);
        cudaFuncSetAttribute(gemm_mma<2>, cudaFuncAttributeMaxDynamicSharedMemorySize, GEMM_SMEM);
        cudaFuncSetAttribute(scores_mma, cudaFuncAttributeMaxDynamicSharedMemorySize, SC_SMEM);
        cudaFuncSetAttribute(context_mma, cudaFuncAttributeMaxDynamicSharedMemorySize, CTX_SMEM);
        initd = 1;
    }

    split_kernel<<<NEL / 1024, 256>>>(Q, pQih, pQil, NEL);
    split_kernel<<<NEL / 1024, 256>>>(K, pKih, pKil, NEL);
    split_kernel<<<NEL / 1024, 256>>>(V, pVih, pVil, NEL);
    split_kernel<<<WEL / 1024, 256>>>(Wq, pWqh, pWql, WEL);
    split_kernel<<<WEL / 1024, 256>>>(Wk, pWkh, pWkl, WEL);
    split_kernel<<<WEL / 1024, 256>>>(Wv, pWvh, pWvl, WEL);
    split_kernel<<<WEL / 1024, 256>>>(Wo, pWoh, pWol, WEL);

    const dim3 gemmGrid(DD / 128, MTOT / 128);          // (8, 64)
    gemm_mma<0><<<gemmGrid, 256, GEMM_SMEM>>>(pQih, pQil, pWqh, pWql, bq, nullptr, pqh, pql, nullptr);
    gemm_mma<0><<<gemmGrid, 256, GEMM_SMEM>>>(pKih, pKil, pWkh, pWkl, bk, nullptr, pkh, pkl, nullptr);
    gemm_mma<0><<<gemmGrid, 256, GEMM_SMEM>>>(pVih, pVil, pWvh, pWvl, bv, nullptr, pvh, pvl, nullptr);

    const dim3 scoreGrid(SS / 128, SS / 128, BB * HH);  // (8, 8, 128)
    scores_mma<<<scoreGrid, 256, SC_SMEM>>>(pqh, pql, pkh, pkl, mask, scores);

    softmax_kernel<<<BB * HH * SS, 256>>>(scores, attn, pah, pal);

    const dim3 ctxGrid(SS / 128, BB * HH);              // (8, 128)
    context_mma<<<ctxGrid, 256, CTX_SMEM>>>(pah, pal, pvh, pvl, pctxh, pctxl);

    gemm_mma<2><<<gemmGrid, 256, GEMM_SMEM>>>(pctxh, pctxl, pWoh, pWol, bo, Q, nullptr, nullptr, out);
}

// round 11
// speedup vs baseline: 3.6674x; 1.4327x over previous
#include <cuda_runtime.h>
#include <cuda_fp16.h>
#include <cstdint>

typedef unsigned int u32;

#define BB  8
#define SS  1024
#define DD  1024
#define HH  16
#define DKK 64
#define MTOT 8192
#define NEL  8388608
#define WEL  1048576
#define AEL  134217728ULL

// ---------------------------------------------------------------------------
// Scratch (__device__ globals; allocation-free rule)
// ---------------------------------------------------------------------------
__device__ __half gQih[NEL], gQil[NEL], gKih[NEL], gKil[NEL], gVih[NEL], gVil[NEL];
__device__ __half gWqh[WEL], gWkh[WEL], gWvh[WEL], gWoh[WEL];
__device__ __half gqh[NEL], gql[NEL], gkh[NEL], gvh[NEL], gvl[NEL];
__device__ __half gattnh[AEL];
__device__ __half gctxh[NEL], gctxl[NEL];

// ---------------------------------------------------------------------------
// Baseline-ISA tensor helpers (compile under compute_103)
// ---------------------------------------------------------------------------
__device__ __forceinline__ u32 smem_u32(const void* p) {
    u32 a;
    asm("{ .reg .u64 t; cvta.to.shared.u64 t, %1; cvt.u32.u64 %0, t; }" : "=r"(a) : "l"(p));
    return a;
}
__device__ __forceinline__ void ldsm4(u32& r0, u32& r1, u32& r2, u32& r3, u32 a) {
    asm volatile("ldmatrix.sync.aligned.m8n8.x4.shared.b16 {%0,%1,%2,%3}, [%4];"
                 : "=r"(r0), "=r"(r1), "=r"(r2), "=r"(r3) : "r"(a));
}
__device__ __forceinline__ void ldsm4t(u32& r0, u32& r1, u32& r2, u32& r3, u32 a) {
    asm volatile("ldmatrix.sync.aligned.m8n8.x4.trans.shared.b16 {%0,%1,%2,%3}, [%4];"
                 : "=r"(r0), "=r"(r1), "=r"(r2), "=r"(r3) : "r"(a));
}
__device__ __forceinline__ void mma_f16(float* c, const u32* a, u32 b0, u32 b1) {
    asm volatile(
        "mma.sync.aligned.m16n8k16.row.col.f32.f16.f16.f32 "
        "{%0,%1,%2,%3}, {%4,%5,%6,%7}, {%8,%9}, {%0,%1,%2,%3};"
        : "+f"(c[0]), "+f"(c[1]), "+f"(c[2]), "+f"(c[3])
        : "r"(a[0]), "r"(a[1]), "r"(a[2]), "r"(a[3]), "r"(b0), "r"(b1));
}
__device__ __forceinline__ void cp16(u32 dst, const void* src) {
    asm volatile("cp.async.cg.shared.global [%0], [%1], 16;" :: "r"(dst), "l"(src));
}
#define CP_COMMIT() asm volatile("cp.async.commit_group;" ::: "memory")
#define CP_WAIT0()  asm volatile("cp.async.wait_group 0;" ::: "memory")
#define CP_WAIT1()  asm volatile("cp.async.wait_group 1;" ::: "memory")

__device__ __forceinline__ void split1(float v, __half& h, __half& l) {
    h = __float2half_rn(v);
    l = __float2half_rn(v - __half2float(h));
}

// ---------------------------------------------------------------------------
// Split fp32 -> (fp16 hi, fp16 lo)
// ---------------------------------------------------------------------------
__global__ __launch_bounds__(256) void split_kernel(const float* __restrict__ x,
                                                    __half* __restrict__ hi,
                                                    __half* __restrict__ lo,
                                                    int n) {
    const int i = (blockIdx.x * 256 + threadIdx.x) * 4;
    if (i >= n) return;
    float4 v = *(const float4*)(x + i);
    __half h0, h1, h2, h3, l0, l1, l2, l3;
    split1(v.x, h0, l0); split1(v.y, h1, l1);
    split1(v.z, h2, l2); split1(v.w, h3, l3);
    __half2 H0; H0.x = h0; H0.y = h1;
    __half2 H1; H1.x = h2; H1.y = h3;
    __half2 L0; L0.x = l0; L0.y = l1;
    __half2 L1; L1.x = l2; L1.y = l3;
    *(__half2*)(hi + i)     = H0;
    *(__half2*)(hi + i + 2) = H1;
    *(__half2*)(lo + i)     = L0;
    *(__half2*)(lo + i + 2) = L1;
}

// fp32 -> fp16 (hi only, for weights)
__global__ __launch_bounds__(256) void conv_kernel(const float* __restrict__ x,
                                                   __half* __restrict__ hi, int n) {
    const int i = (blockIdx.x * 256 + threadIdx.x) * 4;
    if (i >= n) return;
    float4 v = *(const float4*)(x + i);
    __half2 H0; H0.x = __float2half_rn(v.x); H0.y = __float2half_rn(v.y);
    __half2 H1; H1.x = __float2half_rn(v.z); H1.y = __float2half_rn(v.w);
    *(__half2*)(hi + i)     = H0;
    *(__half2*)(hi + i + 2) = H1;
}

// ---------------------------------------------------------------------------
// mma.sync GEMM: C = A[M,K] @ B[N,K]^T (+bias [+Qres]), fp16 2-pass:
//   C = Ah@Bh + Al@Bh    (B residual dropped; B supplied hi-only)
// 128x128 tile, BK=32, cp.async double-buffered, 8 warps (warp tile 64x32)
// MODE 0: fp16 hi/lo scattered to [B,H,S,DK]
// MODE 1: fp16 hi only scattered to [B,H,S,DK]
// MODE 2: fp32 [M,N] + bias + Qres
// ---------------------------------------------------------------------------
#define GST    80                 // smem row stride bytes (40 fp16)
#define GMAT   (128 * GST)        // 10240
#define GSTAGE (3 * GMAT)         // 30720: [Ah][Al][Bh]
#define GEMM_SMEM (2 * GSTAGE)    // 61440

template <int MODE>
__global__ __launch_bounds__(256) void gemm_mma(
    const __half* __restrict__ Ahg, const __half* __restrict__ Alg,
    const __half* __restrict__ Bhg,
    const float* __restrict__ bias, const float* __restrict__ Qres,
    __half* __restrict__ o_hi, __half* __restrict__ o_lo,
    float* __restrict__ o_f) {
    extern __shared__ char smarr[];
    const u32 sb = smem_u32(smarr);
    const int tid = threadIdx.x, lane = tid & 31, wid = tid >> 5;
    const int wm = wid & 1, wn = wid >> 1;
    const int m0 = blockIdx.y * 128, n0 = blockIdx.x * 128;

    float acc[4][4][4];
#pragma unroll
    for (int a = 0; a < 4; ++a)
#pragma unroll
        for (int b = 0; b < 4; ++b)
#pragma unroll
            for (int c = 0; c < 4; ++c) acc[a][b][c] = 0.f;

    const __half* gsrc[3] = {Ahg + (size_t)m0 * DD, Alg + (size_t)m0 * DD,
                             Bhg + (size_t)n0 * DD};

    auto LOAD = [&](int kt, int buf) {
        const int ko = kt * 32;
#pragma unroll
        for (int mat = 0; mat < 3; ++mat)
#pragma unroll
            for (int i = 0; i < 2; ++i) {
                const int ch = tid + i * 256;
                const int row = ch >> 2, c = ch & 3;
                cp16(sb + buf * GSTAGE + mat * GMAT + row * GST + c * 16,
                     gsrc[mat] + (size_t)row * DD + ko + c * 8);
            }
    };

    auto COMP = [&](int buf) {
        const u32 st = sb + buf * GSTAGE;
#pragma unroll
        for (int s = 0; s < 2; ++s) {
            u32 ah[4][4], al[4][4];
#pragma unroll
            for (int mt = 0; mt < 4; ++mt) {
                const int row = wm * 64 + mt * 16 + (lane & 15);
                const int colb = (s * 16 + (lane >> 4) * 8) * 2;
                const u32 ad = st + row * GST + colb;
                ldsm4(ah[mt][0], ah[mt][1], ah[mt][2], ah[mt][3], ad);
                ldsm4(al[mt][0], al[mt][1], al[mt][2], al[mt][3], ad + GMAT);
            }
            u32 bh[2][4];
#pragma unroll
            for (int bt = 0; bt < 2; ++bt) {
                const int row = wn * 32 + bt * 16 + ((lane >> 4) & 1) * 8 + (lane & 7);
                const int colb = (s * 16 + ((lane >> 3) & 1) * 8) * 2;
                const u32 bd = st + 2 * GMAT + row * GST + colb;
                ldsm4(bh[bt][0], bh[bt][1], bh[bt][2], bh[bt][3], bd);
            }
#pragma unroll
            for (int mt = 0; mt < 4; ++mt)
#pragma unroll
                for (int bt = 0; bt < 2; ++bt)
#pragma unroll
                    for (int j = 0; j < 2; ++j) {
                        float* c = acc[mt][bt * 2 + j];
                        mma_f16(c, ah[mt], bh[bt][2 * j], bh[bt][2 * j + 1]);
                        mma_f16(c, al[mt], bh[bt][2 * j], bh[bt][2 * j + 1]);
                    }
        }
    };

    LOAD(0, 0); CP_COMMIT();
    for (int kt = 0; kt < 32; ++kt) {
        const int buf = kt & 1;
        if (kt + 1 < 32) { LOAD(kt + 1, buf ^ 1); CP_COMMIT(); CP_WAIT1(); }
        else             { CP_WAIT0(); }
        __syncthreads();
        COMP(buf);
        __syncthreads();
    }

    const int r0 = lane >> 2, cp = (lane & 3) * 2;
#pragma unroll
    for (int mt = 0; mt < 4; ++mt)
#pragma unroll
        for (int i = 0; i < 2; ++i) {
            const int m = m0 + wm * 64 + mt * 16 + r0 + i * 8;
#pragma unroll
            for (int nt = 0; nt < 4; ++nt) {
                const int n = n0 + wn * 32 + nt * 8 + cp;
                float v0 = acc[mt][nt][i * 2 + 0] + __ldg(&bias[n]);
                float v1 = acc[mt][nt][i * 2 + 1] + __ldg(&bias[n + 1]);
                if (MODE == 0 || MODE == 1) {
                    const int bI = m >> 10, s = m & 1023;
                    const int h = n >> 6, d = n & 63;
                    const size_t o = ((size_t)(bI * HH + h) * SS + s) * DKK + d;
                    __half h0, h1, l0, l1;
                    split1(v0, h0, l0); split1(v1, h1, l1);
                    __half2 hh; hh.x = h0; hh.y = h1;
                    *(__half2*)&o_hi[o] = hh;
                    if (MODE == 0) {
                        __half2 ll; ll.x = l0; ll.y = l1;
                        *(__half2*)&o_lo[o] = ll;
                    }
                } else {
                    const size_t o = (size_t)m * DD + n;
                    float2 qv = *(const float2*)&Qres[o];
                    float2 val; val.x = v0 + qv.x; val.y = v1 + qv.y;
                    *(float2*)&o_f[o] = val;
                }
            }
        }
}

// ---------------------------------------------------------------------------
// scores via mma.sync: per (b,h) 128x128 tile, K=64 single stage
//   S = qh@kh^T + ql@kh^T   (k residual dropped)
// ---------------------------------------------------------------------------
#define SSTR 144
#define SMAT (128 * SSTR)       // 18432
#define SC_SMEM (3 * SMAT)      // 55296

__global__ __launch_bounds__(256) void scores_mma(
    const __half* __restrict__ qh, const __half* __restrict__ ql,
    const __half* __restrict__ kh,
    const unsigned char* __restrict__ mask, float* __restrict__ scores) {
    extern __shared__ char smarr[];
    const u32 sb = smem_u32(smarr);
    const int tid = threadIdx.x, lane = tid & 31, wid = tid >> 5;
    const int wm = wid & 1, wn = wid >> 1;
    const int bh = blockIdx.z;
    const int m0 = blockIdx.y * 128, n0 = blockIdx.x * 128;

    const __half* gsrc[3] = {
        qh + ((size_t)bh * SS + m0) * DKK, ql + ((size_t)bh * SS + m0) * DKK,
        kh + ((size_t)bh * SS + n0) * DKK};
#pragma unroll
    for (int mat = 0; mat < 3; ++mat)
#pragma unroll
        for (int i = 0; i < 4; ++i) {
            const int ch = tid + i * 256;
            const int row = ch >> 3, c = ch & 7;
            cp16(sb + mat * SMAT + row * SSTR + c * 16,
                 gsrc[mat] + (size_t)row * DKK + c * 8);
        }
    CP_COMMIT(); CP_WAIT0();
    __syncthreads();

    float acc[4][4][4];
#pragma unroll
    for (int a = 0; a < 4; ++a)
#pragma unroll
        for (int b = 0; b < 4; ++b)
#pragma unroll
            for (int c = 0; c < 4; ++c) acc[a][b][c] = 0.f;

#pragma unroll
    for (int s = 0; s < 4; ++s) {
        u32 ah[4][4], al[4][4];
#pragma unroll
        for (int mt = 0; mt < 4; ++mt) {
            const int row = wm * 64 + mt * 16 + (lane & 15);
            const int colb = (s * 16 + (lane >> 4) * 8) * 2;
            const u32 ad = sb + row * SSTR + colb;
            ldsm4(ah[mt][0], ah[mt][1], ah[mt][2], ah[mt][3], ad);
            ldsm4(al[mt][0], al[mt][1], al[mt][2], al[mt][3], ad + SMAT);
        }
        u32 bh_[2][4];
#pragma unroll
        for (int bt = 0; bt < 2; ++bt) {
            const int row = wn * 32 + bt * 16 + ((lane >> 4) & 1) * 8 + (lane & 7);
            const int colb = (s * 16 + ((lane >> 3) & 1) * 8) * 2;
            const u32 bd = sb + 2 * SMAT + row * SSTR + colb;
            ldsm4(bh_[bt][0], bh_[bt][1], bh_[bt][2], bh_[bt][3], bd);
        }
#pragma unroll
        for (int mt = 0; mt < 4; ++mt)
#pragma unroll
            for (int bt = 0; bt < 2; ++bt)
#pragma unroll
                for (int j = 0; j < 2; ++j) {
                    float* c = acc[mt][bt * 2 + j];
                    mma_f16(c, ah[mt], bh_[bt][2 * j], bh_[bt][2 * j + 1]);
                    mma_f16(c, al[mt], bh_[bt][2 * j], bh_[bt][2 * j + 1]);
                }
    }

    const int bI = bh >> 4;
    float* srow = scores + (size_t)bh * SS * SS;
    const unsigned char* mrow = mask + (size_t)bI * SS * SS;
    const int r0 = lane >> 2, cp = (lane & 3) * 2;
#pragma unroll
    for (int mt = 0; mt < 4; ++mt)
#pragma unroll
        for (int i = 0; i < 2; ++i) {
            const int m = m0 + wm * 64 + mt * 16 + r0 + i * 8;
#pragma unroll
            for (int nt = 0; nt < 4; ++nt) {
                const int n = n0 + wn * 32 + nt * 8 + cp;
                float v0 = acc[mt][nt][i * 2 + 0] * 0.125f;
                float v1 = acc[mt][nt][i * 2 + 1] * 0.125f;
                uchar2 mk = *(const uchar2*)&mrow[(size_t)m * SS + n];
                if (mk.x) v0 = -1e9f;
                if (mk.y) v1 = -1e9f;
                float2 val; val.x = v0; val.y = v1;
                *(float2*)&srow[(size_t)m * SS + n] = val;
            }
        }
}

// ---------------------------------------------------------------------------
// softmax (row length 1024) — writes fp32 attn + fp16 hi only
// ---------------------------------------------------------------------------
__global__ __launch_bounds__(256) void softmax_kernel(const float* __restrict__ scores,
                                                      float* __restrict__ attn,
                                                      __half* __restrict__ ahi) {
    const size_t row = blockIdx.x;
    const float4* src = (const float4*)(scores + row * SS);
    const int t = threadIdx.x;
    float4 x = src[t];

    float m = fmaxf(fmaxf(x.x, x.y), fmaxf(x.z, x.w));
#pragma unroll
    for (int o = 16; o; o >>= 1) m = fmaxf(m, __shfl_xor_sync(0xffffffffu, m, o));

    __shared__ float smax[8];
    __shared__ float ssum[8];
    const int wid = t >> 5, lane = t & 31;
    if (lane == 0) smax[wid] = m;
    __syncthreads();
    float mx = smax[0];
#pragma unroll
    for (int i = 1; i < 8; ++i) mx = fmaxf(mx, smax[i]);

    float4 e;
    e.x = __expf(x.x - mx); e.y = __expf(x.y - mx);
    e.z = __expf(x.z - mx); e.w = __expf(x.w - mx);
    float s = e.x + e.y + e.z + e.w;
#pragma unroll
    for (int o = 16; o; o >>= 1) s += __shfl_xor_sync(0xffffffffu, s, o);
    if (lane == 0) ssum[wid] = s;
    __syncthreads();
    float tot = 0.f;
#pragma unroll
    for (int i = 0; i < 8; ++i) tot += ssum[i];

    const float inv = 1.0f / tot;
    float4 r = make_float4(e.x * inv, e.y * inv, e.z * inv, e.w * inv);
    ((float4*)(attn + row * SS))[t] = r;

    __half2 H0; H0.x = __float2half_rn(r.x); H0.y = __float2half_rn(r.y);
    __half2 H1; H1.x = __float2half_rn(r.z); H1.y = __float2half_rn(r.w);
    const size_t o = row * SS + t * 4;
    *(__half2*)(ahi + o)     = H0;
    *(__half2*)(ahi + o + 2) = H1;
}

// ---------------------------------------------------------------------------
// context via mma.sync: ctx = attn_h @ (Vh + Vl)  (attn residual dropped)
// CTA tile 128(m) x 64(n), BK=32, double-buffered; V via ldmatrix.trans
// ---------------------------------------------------------------------------
#define CAMAT  (128 * 80)                 // 10240 (attn 128x32 fp16)
#define CVMAT  (32 * 144)                 // 4608  (V 32x64 fp16)
#define CSTAGE (CAMAT + 2 * CVMAT)        // 19456: [Ah][Vh][Vl]
#define CTX_SMEM (2 * CSTAGE)             // 38912

__global__ __launch_bounds__(256) void context_mma(
    const __half* __restrict__ ahg,
    const __half* __restrict__ vhg, const __half* __restrict__ vlg,
    __half* __restrict__ ctxh, __half* __restrict__ ctxl) {
    extern __shared__ char smarr[];
    const u32 sb = smem_u32(smarr);
    const int tid = threadIdx.x, lane = tid & 31, wid = tid >> 5;
    const int wm = wid >> 1, wn = wid & 1;
    const int bh = blockIdx.y;
    const int m0 = blockIdx.x * 128;

    const __half* asrc = ahg + ((size_t)bh * SS + m0) * SS;
    const __half* vsrc[2] = {vhg + (size_t)bh * SS * DKK,
                             vlg + (size_t)bh * SS * DKK};

    float acc[2][4][4];
#pragma unroll
    for (int a = 0; a < 2; ++a)
#pragma unroll
        for (int b = 0; b < 4; ++b)
#pragma unroll
            for (int c = 0; c < 4; ++c) acc[a][b][c] = 0.f;

    auto LOAD = [&](int kt, int buf) {
        const int ko = kt * 32;
#pragma unroll
        for (int i = 0; i < 2; ++i) {
            const int ch = tid + i * 256;
            const int row = ch >> 2, c = ch & 3;
            cp16(sb + buf * CSTAGE + row * 80 + c * 16,
                 asrc + (size_t)row * SS + ko + c * 8);
        }
        const int vr = tid >> 3, vc = tid & 7;
#pragma unroll
        for (int half = 0; half < 2; ++half)
            cp16(sb + buf * CSTAGE + CAMAT + half * CVMAT + vr * 144 + vc * 16,
                 vsrc[half] + (size_t)(ko + vr) * DKK + vc * 8);
    };

    auto COMP = [&](int buf) {
        const u32 st = sb + buf * CSTAGE;
#pragma unroll
        for (int s = 0; s < 2; ++s) {
            u32 ah[2][4];
#pragma unroll
            for (int mt = 0; mt < 2; ++mt) {
                const int row = wm * 32 + mt * 16 + (lane & 15);
                const int colb = (s * 16 + (lane >> 4) * 8) * 2;
                ldsm4(ah[mt][0], ah[mt][1], ah[mt][2], ah[mt][3], st + row * 80 + colb);
            }
            u32 bh_[2][4], bl_[2][4];
#pragma unroll
            for (int bt = 0; bt < 2; ++bt) {
                const int rowk = s * 16 + (lane & 7) + ((lane >> 3) & 1) * 8;
                const int coln = wn * 32 + bt * 16 + ((lane >> 4) & 1) * 8;
                const u32 bd = st + CAMAT + rowk * 144 + coln * 2;
                ldsm4t(bh_[bt][0], bh_[bt][1], bh_[bt][2], bh_[bt][3], bd);
                ldsm4t(bl_[bt][0], bl_[bt][1], bl_[bt][2], bl_[bt][3], bd + CVMAT);
            }
#pragma unroll
            for (int mt = 0; mt < 2; ++mt)
#pragma unroll
                for (int bt = 0; bt < 2; ++bt)
#pragma unroll
                    for (int j = 0; j < 2; ++j) {
                        float* c = acc[mt][bt * 2 + j];
                        mma_f16(c, ah[mt], bh_[bt][2 * j], bh_[bt][2 * j + 1]);
                        mma_f16(c, ah[mt], bl_[bt][2 * j], bl_[bt][2 * j + 1]);
                    }
        }
    };

    LOAD(0, 0); CP_COMMIT();
    for (int kt = 0; kt < 32; ++kt) {
        const int buf = kt & 1;
        if (kt + 1 < 32) { LOAD(kt + 1, buf ^ 1); CP_COMMIT(); CP_WAIT1(); }
        else             { CP_WAIT0(); }
        __syncthreads();
        COMP(buf);
        __syncthreads();
    }

    const int bI = bh >> 4, h = bh & 15;
    const int r0 = lane >> 2, cp = (lane & 3) * 2;
#pragma unroll
    for (int mt = 0; mt < 2; ++mt)
#pragma unroll
        for (int i = 0; i < 2; ++i) {
            const int m = m0 + wm * 32 + mt * 16 + r0 + i * 8;
#pragma unroll
            for (int nt = 0; nt < 4; ++nt) {
                const int n = wn * 32 + nt * 8 + cp;
                float v0 = acc[mt][nt][i * 2 + 0];
                float v1 = acc[mt][nt][i * 2 + 1];
                __half h0, h1, l0, l1;
                split1(v0, h0, l0); split1(v1, h1, l1);
                __half2 hh; hh.x = h0; hh.y = h1;
                __half2 ll; ll.x = l0; ll.y = l1;
                const size_t o = ((size_t)bI * SS + m) * DD + h * DKK + n;
                *(__half2*)&ctxh[o] = hh;
                *(__half2*)&ctxl[o] = ll;
            }
        }
}

// ---------------------------------------------------------------------------
// launch
// ---------------------------------------------------------------------------
extern "C" void kernel_launch(void* const* d_in, const int* in_sizes, int n_in,
                              void* d_out, int out_size) {
    const float* Q  = (const float*)d_in[0];
    const float* K  = (const float*)d_in[1];
    const float* V  = (const float*)d_in[2];
    const unsigned char* mask = (const unsigned char*)d_in[3];
    const float* Wq = (const float*)d_in[4];
    const float* bq = (const float*)d_in[5];
    const float* Wk = (const float*)d_in[6];
    const float* bk = (const float*)d_in[7];
    const float* Wv = (const float*)d_in[8];
    const float* bv = (const float*)d_in[9];
    const float* Wo = (const float*)d_in[10];
    const float* bo = (const float*)d_in[11];

    float* out    = (float*)d_out;
    float* attn   = out + (size_t)BB * SS * DD;
    float* scores = attn + (size_t)BB * HH * SS * SS;

    __half *pQih, *pQil, *pKih, *pKil, *pVih, *pVil;
    __half *pWqh, *pWkh, *pWvh, *pWoh;
    __half *pqh, *pql, *pkh, *pvh, *pvl, *pah, *pctxh, *pctxl;
    cudaGetSymbolAddress((void**)&pQih, gQih); cudaGetSymbolAddress((void**)&pQil, gQil);
    cudaGetSymbolAddress((void**)&pKih, gKih); cudaGetSymbolAddress((void**)&pKil, gKil);
    cudaGetSymbolAddress((void**)&pVih, gVih); cudaGetSymbolAddress((void**)&pVil, gVil);
    cudaGetSymbolAddress((void**)&pWqh, gWqh); cudaGetSymbolAddress((void**)&pWkh, gWkh);
    cudaGetSymbolAddress((void**)&pWvh, gWvh); cudaGetSymbolAddress((void**)&pWoh, gWoh);
    cudaGetSymbolAddress((void**)&pqh, gqh);   cudaGetSymbolAddress((void**)&pql, gql);
    cudaGetSymbolAddress((void**)&pkh, gkh);
    cudaGetSymbolAddress((void**)&pvh, gvh);   cudaGetSymbolAddress((void**)&pvl, gvl);
    cudaGetSymbolAddress((void**)&pah, gattnh);
    cudaGetSymbolAddress((void**)&pctxh, gctxh); cudaGetSymbolAddress((void**)&pctxl, gctxl);

    static int initd = 0;
    if (!initd) {
        cudaFuncSetAttribute(gemm_mma<0>, cudaFuncAttributeMaxDynamicSharedMemorySize, GEMM_SMEM);
        cudaFuncSetAttribute(gemm_mma<1>, cudaFuncAttributeMaxDynamicSharedMemorySize, GEMM_SMEM);
        cudaFuncSetAttribute(gemm_mma<2>, cudaFuncAttributeMaxDynamicSharedMemorySize, GEMM_SMEM);
        cudaFuncSetAttribute(scores_mma, cudaFuncAttributeMaxDynamicSharedMemorySize, SC_SMEM);
        cudaFuncSetAttribute(context_mma, cudaFuncAttributeMaxDynamicSharedMemorySize, CTX_SMEM);
        initd = 1;
    }

    split_kernel<<<NEL / 1024, 256>>>(Q, pQih, pQil, NEL);
    split_kernel<<<NEL / 1024, 256>>>(K, pKih, pKil, NEL);
    split_kernel<<<NEL / 1024, 256>>>(V, pVih, pVil, NEL);
    conv_kernel<<<WEL / 1024, 256>>>(Wq, pWqh, WEL);
    conv_kernel<<<WEL / 1024, 256>>>(Wk, pWkh, WEL);
    conv_kernel<<<WEL / 1024, 256>>>(Wv, pWvh, WEL);
    conv_kernel<<<WEL / 1024, 256>>>(Wo, pWoh, WEL);

    const dim3 gemmGrid(DD / 128, MTOT / 128);          // (8, 64)
    gemm_mma<0><<<gemmGrid, 256, GEMM_SMEM>>>(pQih, pQil, pWqh, bq, nullptr, pqh, pql, nullptr);
    gemm_mma<1><<<gemmGrid, 256, GEMM_SMEM>>>(pKih, pKil, pWkh, bk, nullptr, pkh, nullptr, nullptr);
    gemm_mma<0><<<gemmGrid, 256, GEMM_SMEM>>>(pVih, pVil, pWvh, bv, nullptr, pvh, pvl, nullptr);

    const dim3 scoreGrid(SS / 128, SS / 128, BB * HH);  // (8, 8, 128)
    scores_mma<<<scoreGrid, 256, SC_SMEM>>>(pqh, pql, pkh, mask, scores);

    softmax_kernel<<<BB * HH * SS, 256>>>(scores, attn, pah);

    const dim3 ctxGrid(SS / 128, BB * HH);              // (8, 128)
    context_mma<<<ctxGrid, 256, CTX_SMEM>>>(pah, pvh, pvl, pctxh, pctxl);

    gemm_mma<2><<<gemmGrid, 256, GEMM_SMEM>>>(pctxh, pctxl, pWoh, bo, Q, nullptr, nullptr, out);
}

// round 12
// speedup vs baseline: 4.0848x; 1.1138x over previous
#include <cuda_runtime.h>
#include <cuda_fp16.h>
#include <cstdint>

typedef unsigned int u32;

#define BB  8
#define SS  1024
#define DD  1024
#define HH  16
#define DKK 64
#define MTOT 8192
#define NEL  8388608
#define WEL  1048576
#define AEL  134217728ULL

// ---------------------------------------------------------------------------
// Scratch (__device__ globals; allocation-free rule)
// ---------------------------------------------------------------------------
__device__ __half gQih[NEL], gQil[NEL], gKih[NEL], gKil[NEL], gVih[NEL];
__device__ __half gWqh[WEL], gWkh[WEL], gWvh[WEL], gWoh[WEL];
__device__ __half gqh[NEL], gql[NEL], gkh[NEL], gvh[NEL];
__device__ __half gattnh[AEL];
__device__ __half gctxh[NEL];

// ---------------------------------------------------------------------------
// Baseline-ISA tensor helpers (compile under compute_103)
// ---------------------------------------------------------------------------
__device__ __forceinline__ u32 smem_u32(const void* p) {
    u32 a;
    asm("{ .reg .u64 t; cvta.to.shared.u64 t, %1; cvt.u32.u64 %0, t; }" : "=r"(a) : "l"(p));
    return a;
}
__device__ __forceinline__ void ldsm4(u32& r0, u32& r1, u32& r2, u32& r3, u32 a) {
    asm volatile("ldmatrix.sync.aligned.m8n8.x4.shared.b16 {%0,%1,%2,%3}, [%4];"
                 : "=r"(r0), "=r"(r1), "=r"(r2), "=r"(r3) : "r"(a));
}
__device__ __forceinline__ void ldsm4t(u32& r0, u32& r1, u32& r2, u32& r3, u32 a) {
    asm volatile("ldmatrix.sync.aligned.m8n8.x4.trans.shared.b16 {%0,%1,%2,%3}, [%4];"
                 : "=r"(r0), "=r"(r1), "=r"(r2), "=r"(r3) : "r"(a));
}
__device__ __forceinline__ void mma_f16(float* c, const u32* a, u32 b0, u32 b1) {
    asm volatile(
        "mma.sync.aligned.m16n8k16.row.col.f32.f16.f16.f32 "
        "{%0,%1,%2,%3}, {%4,%5,%6,%7}, {%8,%9}, {%0,%1,%2,%3};"
        : "+f"(c[0]), "+f"(c[1]), "+f"(c[2]), "+f"(c[3])
        : "r"(a[0]), "r"(a[1]), "r"(a[2]), "r"(a[3]), "r"(b0), "r"(b1));
}
__device__ __forceinline__ void cp16(u32 dst, const void* src) {
    asm volatile("cp.async.cg.shared.global [%0], [%1], 16;" :: "r"(dst), "l"(src));
}
#define CP_COMMIT() asm volatile("cp.async.commit_group;" ::: "memory")
#define CP_WAIT0()  asm volatile("cp.async.wait_group 0;" ::: "memory")
#define CP_WAIT1()  asm volatile("cp.async.wait_group 1;" ::: "memory")

__device__ __forceinline__ void split1(float v, __half& h, __half& l) {
    h = __float2half_rn(v);
    l = __float2half_rn(v - __half2float(h));
}

// ---------------------------------------------------------------------------
// Split fp32 -> (fp16 hi, fp16 lo)
// ---------------------------------------------------------------------------
__global__ __launch_bounds__(256) void split_kernel(const float* __restrict__ x,
                                                    __half* __restrict__ hi,
                                                    __half* __restrict__ lo,
                                                    int n) {
    const int i = (blockIdx.x * 256 + threadIdx.x) * 4;
    if (i >= n) return;
    float4 v = *(const float4*)(x + i);
    __half h0, h1, h2, h3, l0, l1, l2, l3;
    split1(v.x, h0, l0); split1(v.y, h1, l1);
    split1(v.z, h2, l2); split1(v.w, h3, l3);
    __half2 H0; H0.x = h0; H0.y = h1;
    __half2 H1; H1.x = h2; H1.y = h3;
    __half2 L0; L0.x = l0; L0.y = l1;
    __half2 L1; L1.x = l2; L1.y = l3;
    *(__half2*)(hi + i)     = H0;
    *(__half2*)(hi + i + 2) = H1;
    *(__half2*)(lo + i)     = L0;
    *(__half2*)(lo + i + 2) = L1;
}

// fp32 -> fp16 hi only
__global__ __launch_bounds__(256) void conv_kernel(const float* __restrict__ x,
                                                   __half* __restrict__ hi, int n) {
    const int i = (blockIdx.x * 256 + threadIdx.x) * 4;
    if (i >= n) return;
    float4 v = *(const float4*)(x + i);
    __half2 H0; H0.x = __float2half_rn(v.x); H0.y = __float2half_rn(v.y);
    __half2 H1; H1.x = __float2half_rn(v.z); H1.y = __float2half_rn(v.w);
    *(__half2*)(hi + i)     = H0;
    *(__half2*)(hi + i + 2) = H1;
}

// ---------------------------------------------------------------------------
// Shared epilogue helper
// ---------------------------------------------------------------------------
#define GST    80                 // smem row stride bytes (40 fp16)
#define GMAT   (128 * GST)        // 10240

// ---------------------------------------------------------------------------
// 2-pass GEMM: C = (Ah+Al) @ Bh^T (+bias); MODE 0: hi/lo out, MODE 1: hi out
// ---------------------------------------------------------------------------
#define GSTAGE2 (3 * GMAT)        // [Ah][Al][Bh]
#define GEMM2_SMEM (2 * GSTAGE2)  // 61440

template <int MODE>
__global__ __launch_bounds__(256) void gemm_mma2(
    const __half* __restrict__ Ahg, const __half* __restrict__ Alg,
    const __half* __restrict__ Bhg,
    const float* __restrict__ bias,
    __half* __restrict__ o_hi, __half* __restrict__ o_lo) {
    extern __shared__ char smarr[];
    const u32 sb = smem_u32(smarr);
    const int tid = threadIdx.x, lane = tid & 31, wid = tid >> 5;
    const int wm = wid & 1, wn = wid >> 1;
    const int m0 = blockIdx.y * 128, n0 = blockIdx.x * 128;

    float acc[4][4][4];
#pragma unroll
    for (int a = 0; a < 4; ++a)
#pragma unroll
        for (int b = 0; b < 4; ++b)
#pragma unroll
            for (int c = 0; c < 4; ++c) acc[a][b][c] = 0.f;

    const __half* gsrc[3] = {Ahg + (size_t)m0 * DD, Alg + (size_t)m0 * DD,
                             Bhg + (size_t)n0 * DD};

    auto LOAD = [&](int kt, int buf) {
        const int ko = kt * 32;
#pragma unroll
        for (int mat = 0; mat < 3; ++mat)
#pragma unroll
            for (int i = 0; i < 2; ++i) {
                const int ch = tid + i * 256;
                const int row = ch >> 2, c = ch & 3;
                cp16(sb + buf * GSTAGE2 + mat * GMAT + row * GST + c * 16,
                     gsrc[mat] + (size_t)row * DD + ko + c * 8);
            }
    };

    auto COMP = [&](int buf) {
        const u32 st = sb + buf * GSTAGE2;
#pragma unroll
        for (int s = 0; s < 2; ++s) {
            u32 ah[4][4], al[4][4];
#pragma unroll
            for (int mt = 0; mt < 4; ++mt) {
                const int row = wm * 64 + mt * 16 + (lane & 15);
                const int colb = (s * 16 + (lane >> 4) * 8) * 2;
                const u32 ad = st + row * GST + colb;
                ldsm4(ah[mt][0], ah[mt][1], ah[mt][2], ah[mt][3], ad);
                ldsm4(al[mt][0], al[mt][1], al[mt][2], al[mt][3], ad + GMAT);
            }
            u32 bh[2][4];
#pragma unroll
            for (int bt = 0; bt < 2; ++bt) {
                const int row = wn * 32 + bt * 16 + ((lane >> 4) & 1) * 8 + (lane & 7);
                const int colb = (s * 16 + ((lane >> 3) & 1) * 8) * 2;
                const u32 bd = st + 2 * GMAT + row * GST + colb;
                ldsm4(bh[bt][0], bh[bt][1], bh[bt][2], bh[bt][3], bd);
            }
#pragma unroll
            for (int mt = 0; mt < 4; ++mt)
#pragma unroll
                for (int bt = 0; bt < 2; ++bt)
#pragma unroll
                    for (int j = 0; j < 2; ++j) {
                        float* c = acc[mt][bt * 2 + j];
                        mma_f16(c, ah[mt], bh[bt][2 * j], bh[bt][2 * j + 1]);
                        mma_f16(c, al[mt], bh[bt][2 * j], bh[bt][2 * j + 1]);
                    }
        }
    };

    LOAD(0, 0); CP_COMMIT();
    for (int kt = 0; kt < 32; ++kt) {
        const int buf = kt & 1;
        if (kt + 1 < 32) { LOAD(kt + 1, buf ^ 1); CP_COMMIT(); CP_WAIT1(); }
        else             { CP_WAIT0(); }
        __syncthreads();
        COMP(buf);
        __syncthreads();
    }

    const int r0 = lane >> 2, cp = (lane & 3) * 2;
#pragma unroll
    for (int mt = 0; mt < 4; ++mt)
#pragma unroll
        for (int i = 0; i < 2; ++i) {
            const int m = m0 + wm * 64 + mt * 16 + r0 + i * 8;
#pragma unroll
            for (int nt = 0; nt < 4; ++nt) {
                const int n = n0 + wn * 32 + nt * 8 + cp;
                float v0 = acc[mt][nt][i * 2 + 0] + __ldg(&bias[n]);
                float v1 = acc[mt][nt][i * 2 + 1] + __ldg(&bias[n + 1]);
                const int bI = m >> 10, s = m & 1023;
                const int h = n >> 6, d = n & 63;
                const size_t o = ((size_t)(bI * HH + h) * SS + s) * DKK + d;
                __half h0, h1, l0, l1;
                split1(v0, h0, l0); split1(v1, h1, l1);
                __half2 hh; hh.x = h0; hh.y = h1;
                *(__half2*)&o_hi[o] = hh;
                if (MODE == 0) {
                    __half2 ll; ll.x = l0; ll.y = l1;
                    *(__half2*)&o_lo[o] = ll;
                }
            }
        }
}

// ---------------------------------------------------------------------------
// 1-pass GEMM: C = Ah @ Bh^T (+bias [+Qres])
// MODE 1: fp16 hi scattered to [B,H,S,DK];  MODE 2: fp32 [M,N] + bias + Qres
// ---------------------------------------------------------------------------
#define GSTAGE1 (2 * GMAT)        // [Ah][Bh]
#define GEMM1_SMEM (2 * GSTAGE1)  // 40960

template <int MODE>
__global__ __launch_bounds__(256) void gemm_mma1(
    const __half* __restrict__ Ahg, const __half* __restrict__ Bhg,
    const float* __restrict__ bias, const float* __restrict__ Qres,
    __half* __restrict__ o_hi, float* __restrict__ o_f) {
    extern __shared__ char smarr[];
    const u32 sb = smem_u32(smarr);
    const int tid = threadIdx.x, lane = tid & 31, wid = tid >> 5;
    const int wm = wid & 1, wn = wid >> 1;
    const int m0 = blockIdx.y * 128, n0 = blockIdx.x * 128;

    float acc[4][4][4];
#pragma unroll
    for (int a = 0; a < 4; ++a)
#pragma unroll
        for (int b = 0; b < 4; ++b)
#pragma unroll
            for (int c = 0; c < 4; ++c) acc[a][b][c] = 0.f;

    const __half* gsrc[2] = {Ahg + (size_t)m0 * DD, Bhg + (size_t)n0 * DD};

    auto LOAD = [&](int kt, int buf) {
        const int ko = kt * 32;
#pragma unroll
        for (int mat = 0; mat < 2; ++mat)
#pragma unroll
            for (int i = 0; i < 2; ++i) {
                const int ch = tid + i * 256;
                const int row = ch >> 2, c = ch & 3;
                cp16(sb + buf * GSTAGE1 + mat * GMAT + row * GST + c * 16,
                     gsrc[mat] + (size_t)row * DD + ko + c * 8);
            }
    };

    auto COMP = [&](int buf) {
        const u32 st = sb + buf * GSTAGE1;
#pragma unroll
        for (int s = 0; s < 2; ++s) {
            u32 ah[4][4];
#pragma unroll
            for (int mt = 0; mt < 4; ++mt) {
                const int row = wm * 64 + mt * 16 + (lane & 15);
                const int colb = (s * 16 + (lane >> 4) * 8) * 2;
                ldsm4(ah[mt][0], ah[mt][1], ah[mt][2], ah[mt][3], st + row * GST + colb);
            }
            u32 bh[2][4];
#pragma unroll
            for (int bt = 0; bt < 2; ++bt) {
                const int row = wn * 32 + bt * 16 + ((lane >> 4) & 1) * 8 + (lane & 7);
                const int colb = (s * 16 + ((lane >> 3) & 1) * 8) * 2;
                ldsm4(bh[bt][0], bh[bt][1], bh[bt][2], bh[bt][3],
                      st + GMAT + row * GST + colb);
            }
#pragma unroll
            for (int mt = 0; mt < 4; ++mt)
#pragma unroll
                for (int bt = 0; bt < 2; ++bt)
#pragma unroll
                    for (int j = 0; j < 2; ++j)
                        mma_f16(acc[mt][bt * 2 + j], ah[mt], bh[bt][2 * j], bh[bt][2 * j + 1]);
        }
    };

    LOAD(0, 0); CP_COMMIT();
    for (int kt = 0; kt < 32; ++kt) {
        const int buf = kt & 1;
        if (kt + 1 < 32) { LOAD(kt + 1, buf ^ 1); CP_COMMIT(); CP_WAIT1(); }
        else             { CP_WAIT0(); }
        __syncthreads();
        COMP(buf);
        __syncthreads();
    }

    const int r0 = lane >> 2, cp = (lane & 3) * 2;
#pragma unroll
    for (int mt = 0; mt < 4; ++mt)
#pragma unroll
        for (int i = 0; i < 2; ++i) {
            const int m = m0 + wm * 64 + mt * 16 + r0 + i * 8;
#pragma unroll
            for (int nt = 0; nt < 4; ++nt) {
                const int n = n0 + wn * 32 + nt * 8 + cp;
                float v0 = acc[mt][nt][i * 2 + 0] + __ldg(&bias[n]);
                float v1 = acc[mt][nt][i * 2 + 1] + __ldg(&bias[n + 1]);
                if (MODE == 1) {
                    const int bI = m >> 10, s = m & 1023;
                    const int h = n >> 6, d = n & 63;
                    const size_t o = ((size_t)(bI * HH + h) * SS + s) * DKK + d;
                    __half2 hh;
                    hh.x = __float2half_rn(v0); hh.y = __float2half_rn(v1);
                    *(__half2*)&o_hi[o] = hh;
                } else {
                    const size_t o = (size_t)m * DD + n;
                    float2 qv = *(const float2*)&Qres[o];
                    float2 val; val.x = v0 + qv.x; val.y = v1 + qv.y;
                    *(float2*)&o_f[o] = val;
                }
            }
        }
}

// ---------------------------------------------------------------------------
// scores via mma.sync: per (b,h) 128x128 tile, K=64 single stage
//   S = qh@kh^T + ql@kh^T
// ---------------------------------------------------------------------------
#define SSTR 144
#define SMAT (128 * SSTR)       // 18432
#define SC_SMEM (3 * SMAT)      // 55296

__global__ __launch_bounds__(256) void scores_mma(
    const __half* __restrict__ qh, const __half* __restrict__ ql,
    const __half* __restrict__ kh,
    const unsigned char* __restrict__ mask, float* __restrict__ scores) {
    extern __shared__ char smarr[];
    const u32 sb = smem_u32(smarr);
    const int tid = threadIdx.x, lane = tid & 31, wid = tid >> 5;
    const int wm = wid & 1, wn = wid >> 1;
    const int bh = blockIdx.z;
    const int m0 = blockIdx.y * 128, n0 = blockIdx.x * 128;

    const __half* gsrc[3] = {
        qh + ((size_t)bh * SS + m0) * DKK, ql + ((size_t)bh * SS + m0) * DKK,
        kh + ((size_t)bh * SS + n0) * DKK};
#pragma unroll
    for (int mat = 0; mat < 3; ++mat)
#pragma unroll
        for (int i = 0; i < 4; ++i) {
            const int ch = tid + i * 256;
            const int row = ch >> 3, c = ch & 7;
            cp16(sb + mat * SMAT + row * SSTR + c * 16,
                 gsrc[mat] + (size_t)row * DKK + c * 8);
        }
    CP_COMMIT(); CP_WAIT0();
    __syncthreads();

    float acc[4][4][4];
#pragma unroll
    for (int a = 0; a < 4; ++a)
#pragma unroll
        for (int b = 0; b < 4; ++b)
#pragma unroll
            for (int c = 0; c < 4; ++c) acc[a][b][c] = 0.f;

#pragma unroll
    for (int s = 0; s < 4; ++s) {
        u32 ah[4][4], al[4][4];
#pragma unroll
        for (int mt = 0; mt < 4; ++mt) {
            const int row = wm * 64 + mt * 16 + (lane & 15);
            const int colb = (s * 16 + (lane >> 4) * 8) * 2;
            const u32 ad = sb + row * SSTR + colb;
            ldsm4(ah[mt][0], ah[mt][1], ah[mt][2], ah[mt][3], ad);
            ldsm4(al[mt][0], al[mt][1], al[mt][2], al[mt][3], ad + SMAT);
        }
        u32 bh_[2][4];
#pragma unroll
        for (int bt = 0; bt < 2; ++bt) {
            const int row = wn * 32 + bt * 16 + ((lane >> 4) & 1) * 8 + (lane & 7);
            const int colb = (s * 16 + ((lane >> 3) & 1) * 8) * 2;
            ldsm4(bh_[bt][0], bh_[bt][1], bh_[bt][2], bh_[bt][3],
                  sb + 2 * SMAT + row * SSTR + colb);
        }
#pragma unroll
        for (int mt = 0; mt < 4; ++mt)
#pragma unroll
            for (int bt = 0; bt < 2; ++bt)
#pragma unroll
                for (int j = 0; j < 2; ++j) {
                    float* c = acc[mt][bt * 2 + j];
                    mma_f16(c, ah[mt], bh_[bt][2 * j], bh_[bt][2 * j + 1]);
                    mma_f16(c, al[mt], bh_[bt][2 * j], bh_[bt][2 * j + 1]);
                }
    }

    const int bI = bh >> 4;
    float* srow = scores + (size_t)bh * SS * SS;
    const unsigned char* mrow = mask + (size_t)bI * SS * SS;
    const int r0 = lane >> 2, cp = (lane & 3) * 2;
#pragma unroll
    for (int mt = 0; mt < 4; ++mt)
#pragma unroll
        for (int i = 0; i < 2; ++i) {
            const int m = m0 + wm * 64 + mt * 16 + r0 + i * 8;
#pragma unroll
            for (int nt = 0; nt < 4; ++nt) {
                const int n = n0 + wn * 32 + nt * 8 + cp;
                float v0 = acc[mt][nt][i * 2 + 0] * 0.125f;
                float v1 = acc[mt][nt][i * 2 + 1] * 0.125f;
                uchar2 mk = *(const uchar2*)&mrow[(size_t)m * SS + n];
                if (mk.x) v0 = -1e9f;
                if (mk.y) v1 = -1e9f;
                float2 val; val.x = v0; val.y = v1;
                *(float2*)&srow[(size_t)m * SS + n] = val;
            }
        }
}

// ---------------------------------------------------------------------------
// softmax (row length 1024) — writes fp32 attn + fp16 hi
// ---------------------------------------------------------------------------
__global__ __launch_bounds__(256) void softmax_kernel(const float* __restrict__ scores,
                                                      float* __restrict__ attn,
                                                      __half* __restrict__ ahi) {
    const size_t row = blockIdx.x;
    const float4* src = (const float4*)(scores + row * SS);
    const int t = threadIdx.x;
    float4 x = src[t];

    float m = fmaxf(fmaxf(x.x, x.y), fmaxf(x.z, x.w));
#pragma unroll
    for (int o = 16; o; o >>= 1) m = fmaxf(m, __shfl_xor_sync(0xffffffffu, m, o));

    __shared__ float smax[8];
    __shared__ float ssum[8];
    const int wid = t >> 5, lane = t & 31;
    if (lane == 0) smax[wid] = m;
    __syncthreads();
    float mx = smax[0];
#pragma unroll
    for (int i = 1; i < 8; ++i) mx = fmaxf(mx, smax[i]);

    float4 e;
    e.x = __expf(x.x - mx); e.y = __expf(x.y - mx);
    e.z = __expf(x.z - mx); e.w = __expf(x.w - mx);
    float s = e.x + e.y + e.z + e.w;
#pragma unroll
    for (int o = 16; o; o >>= 1) s += __shfl_xor_sync(0xffffffffu, s, o);
    if (lane == 0) ssum[wid] = s;
    __syncthreads();
    float tot = 0.f;
#pragma unroll
    for (int i = 0; i < 8; ++i) tot += ssum[i];

    const float inv = 1.0f / tot;
    float4 r = make_float4(e.x * inv, e.y * inv, e.z * inv, e.w * inv);
    ((float4*)(attn + row * SS))[t] = r;

    __half2 H0; H0.x = __float2half_rn(r.x); H0.y = __float2half_rn(r.y);
    __half2 H1; H1.x = __float2half_rn(r.z); H1.y = __float2half_rn(r.w);
    const size_t o = row * SS + t * 4;
    *(__half2*)(ahi + o)     = H0;
    *(__half2*)(ahi + o + 2) = H1;
}

// ---------------------------------------------------------------------------
// context (1-pass): ctx = attn_h @ Vh, writes ctx hi only
// CTA tile 128(m) x 64(n), BK=32, double-buffered; V via ldmatrix.trans
// ---------------------------------------------------------------------------
#define CAMAT  (128 * 80)                 // 10240
#define CVMAT  (32 * 144)                 // 4608
#define CSTAGE (CAMAT + CVMAT)            // 14848: [Ah][Vh]
#define CTX_SMEM (2 * CSTAGE)             // 29696

__global__ __launch_bounds__(256) void context_mma(
    const __half* __restrict__ ahg, const __half* __restrict__ vhg,
    __half* __restrict__ ctxh) {
    extern __shared__ char smarr[];
    const u32 sb = smem_u32(smarr);
    const int tid = threadIdx.x, lane = tid & 31, wid = tid >> 5;
    const int wm = wid >> 1, wn = wid & 1;
    const int bh = blockIdx.y;
    const int m0 = blockIdx.x * 128;

    const __half* asrc = ahg + ((size_t)bh * SS + m0) * SS;
    const __half* vsrc = vhg + (size_t)bh * SS * DKK;

    float acc[2][4][4];
#pragma unroll
    for (int a = 0; a < 2; ++a)
#pragma unroll
        for (int b = 0; b < 4; ++b)
#pragma unroll
            for (int c = 0; c < 4; ++c) acc[a][b][c] = 0.f;

    auto LOAD = [&](int kt, int buf) {
        const int ko = kt * 32;
#pragma unroll
        for (int i = 0; i < 2; ++i) {
            const int ch = tid + i * 256;
            const int row = ch >> 2, c = ch & 3;
            cp16(sb + buf * CSTAGE + row * 80 + c * 16,
                 asrc + (size_t)row * SS + ko + c * 8);
        }
        const int vr = tid >> 3, vc = tid & 7;
        cp16(sb + buf * CSTAGE + CAMAT + vr * 144 + vc * 16,
             vsrc + (size_t)(ko + vr) * DKK + vc * 8);
    };

    auto COMP = [&](int buf) {
        const u32 st = sb + buf * CSTAGE;
#pragma unroll
        for (int s = 0; s < 2; ++s) {
            u32 ah[2][4];
#pragma unroll
            for (int mt = 0; mt < 2; ++mt) {
                const int row = wm * 32 + mt * 16 + (lane & 15);
                const int colb = (s * 16 + (lane >> 4) * 8) * 2;
                ldsm4(ah[mt][0], ah[mt][1], ah[mt][2], ah[mt][3], st + row * 80 + colb);
            }
            u32 bh_[2][4];
#pragma unroll
            for (int bt = 0; bt < 2; ++bt) {
                const int rowk = s * 16 + (lane & 7) + ((lane >> 3) & 1) * 8;
                const int coln = wn * 32 + bt * 16 + ((lane >> 4) & 1) * 8;
                ldsm4t(bh_[bt][0], bh_[bt][1], bh_[bt][2], bh_[bt][3],
                       st + CAMAT + rowk * 144 + coln * 2);
            }
#pragma unroll
            for (int mt = 0; mt < 2; ++mt)
#pragma unroll
                for (int bt = 0; bt < 2; ++bt)
#pragma unroll
                    for (int j = 0; j < 2; ++j)
                        mma_f16(acc[mt][bt * 2 + j], ah[mt], bh_[bt][2 * j], bh_[bt][2 * j + 1]);
        }
    };

    LOAD(0, 0); CP_COMMIT();
    for (int kt = 0; kt < 32; ++kt) {
        const int buf = kt & 1;
        if (kt + 1 < 32) { LOAD(kt + 1, buf ^ 1); CP_COMMIT(); CP_WAIT1(); }
        else             { CP_WAIT0(); }
        __syncthreads();
        COMP(buf);
        __syncthreads();
    }

    const int bI = bh >> 4, h = bh & 15;
    const int r0 = lane >> 2, cp = (lane & 3) * 2;
#pragma unroll
    for (int mt = 0; mt < 2; ++mt)
#pragma unroll
        for (int i = 0; i < 2; ++i) {
            const int m = m0 + wm * 32 + mt * 16 + r0 + i * 8;
#pragma unroll
            for (int nt = 0; nt < 4; ++nt) {
                const int n = wn * 32 + nt * 8 + cp;
                __half2 hh;
                hh.x = __float2half_rn(acc[mt][nt][i * 2 + 0]);
                hh.y = __float2half_rn(acc[mt][nt][i * 2 + 1]);
                const size_t o = ((size_t)bI * SS + m) * DD + h * DKK + n;
                *(__half2*)&ctxh[o] = hh;
            }
        }
}

// ---------------------------------------------------------------------------
// launch
// ---------------------------------------------------------------------------
extern "C" void kernel_launch(void* const* d_in, const int* in_sizes, int n_in,
                              void* d_out, int out_size) {
    const float* Q  = (const float*)d_in[0];
    const float* K  = (const float*)d_in[1];
    const float* V  = (const float*)d_in[2];
    const unsigned char* mask = (const unsigned char*)d_in[3];
    const float* Wq = (const float*)d_in[4];
    const float* bq = (const float*)d_in[5];
    const float* Wk = (const float*)d_in[6];
    const float* bk = (const float*)d_in[7];
    const float* Wv = (const float*)d_in[8];
    const float* bv = (const float*)d_in[9];
    const float* Wo = (const float*)d_in[10];
    const float* bo = (const float*)d_in[11];

    float* out    = (float*)d_out;
    float* attn   = out + (size_t)BB * SS * DD;
    float* scores = attn + (size_t)BB * HH * SS * SS;

    __half *pQih, *pQil, *pKih, *pKil, *pVih;
    __half *pWqh, *pWkh, *pWvh, *pWoh;
    __half *pqh, *pql, *pkh, *pvh, *pah, *pctxh;
    cudaGetSymbolAddress((void**)&pQih, gQih); cudaGetSymbolAddress((void**)&pQil, gQil);
    cudaGetSymbolAddress((void**)&pKih, gKih); cudaGetSymbolAddress((void**)&pKil, gKil);
    cudaGetSymbolAddress((void**)&pVih, gVih);
    cudaGetSymbolAddress((void**)&pWqh, gWqh); cudaGetSymbolAddress((void**)&pWkh, gWkh);
    cudaGetSymbolAddress((void**)&pWvh, gWvh); cudaGetSymbolAddress((void**)&pWoh, gWoh);
    cudaGetSymbolAddress((void**)&pqh, gqh);   cudaGetSymbolAddress((void**)&pql, gql);
    cudaGetSymbolAddress((void**)&pkh, gkh);   cudaGetSymbolAddress((void**)&pvh, gvh);
    cudaGetSymbolAddress((void**)&pah, gattnh);
    cudaGetSymbolAddress((void**)&pctxh, gctxh);

    static int initd = 0;
    if (!initd) {
        cudaFuncSetAttribute(gemm_mma2<0>, cudaFuncAttributeMaxDynamicSharedMemorySize, GEMM2_SMEM);
        cudaFuncSetAttribute(gemm_mma2<1>, cudaFuncAttributeMaxDynamicSharedMemorySize, GEMM2_SMEM);
        cudaFuncSetAttribute(gemm_mma1<1>, cudaFuncAttributeMaxDynamicSharedMemorySize, GEMM1_SMEM);
        cudaFuncSetAttribute(gemm_mma1<2>, cudaFuncAttributeMaxDynamicSharedMemorySize, GEMM1_SMEM);
        cudaFuncSetAttribute(scores_mma, cudaFuncAttributeMaxDynamicSharedMemorySize, SC_SMEM);
        cudaFuncSetAttribute(context_mma, cudaFuncAttributeMaxDynamicSharedMemorySize, CTX_SMEM);
        initd = 1;
    }

    split_kernel<<<NEL / 1024, 256>>>(Q, pQih, pQil, NEL);
    split_kernel<<<NEL / 1024, 256>>>(K, pKih, pKil, NEL);
    conv_kernel<<<NEL / 1024, 256>>>(V, pVih, NEL);
    conv_kernel<<<WEL / 1024, 256>>>(Wq, pWqh, WEL);
    conv_kernel<<<WEL / 1024, 256>>>(Wk, pWkh, WEL);
    conv_kernel<<<WEL / 1024, 256>>>(Wv, pWvh, WEL);
    conv_kernel<<<WEL / 1024, 256>>>(Wo, pWoh, WEL);

    const dim3 gemmGrid(DD / 128, MTOT / 128);          // (8, 64)
    gemm_mma2<0><<<gemmGrid, 256, GEMM2_SMEM>>>(pQih, pQil, pWqh, bq, pqh, pql);
    gemm_mma2<1><<<gemmGrid, 256, GEMM2_SMEM>>>(pKih, pKil, pWkh, bk, pkh, nullptr);
    gemm_mma1<1><<<gemmGrid, 256, GEMM1_SMEM>>>(pVih, pWvh, bv, nullptr, pvh, nullptr);

    const dim3 scoreGrid(SS / 128, SS / 128, BB * HH);  // (8, 8, 128)
    scores_mma<<<scoreGrid, 256, SC_SMEM>>>(pqh, pql, pkh, mask, scores);

    softmax_kernel<<<BB * HH * SS, 256>>>(scores, attn, pah);

    const dim3 ctxGrid(SS / 128, BB * HH);              // (8, 128)
    context_mma<<<ctxGrid, 256, CTX_SMEM>>>(pah, pvh, pctxh);

    gemm_mma1<2><<<gemmGrid, 256, GEMM1_SMEM>>>(pctxh, pWoh, bo, Q, nullptr, out);
}

// round 14
// speedup vs baseline: 4.7163x; 1.1546x over previous
#include <cuda_runtime.h>
#include <cuda_fp16.h>
#include <cstdint>

typedef unsigned int u32;

#define BB  8
#define SS  1024
#define DD  1024
#define HH  16
#define DKK 64
#define MTOT 8192
#define NEL  8388608
#define WEL  1048576
#define AEL  134217728ULL

// ---------------------------------------------------------------------------
// Scratch (__device__ globals; allocation-free rule)
// ---------------------------------------------------------------------------
__device__ __half gQih[NEL], gKih[NEL], gVih[NEL];
__device__ __half gWqh[WEL], gWkh[WEL], gWvh[WEL], gWoh[WEL];
__device__ __half gqh[NEL], gql[NEL], gkh[NEL], gvh[NEL];
__device__ __half gattnh[AEL];
__device__ __half gctxh[NEL];

// ---------------------------------------------------------------------------
// Baseline-ISA tensor helpers (compile under compute_103)
// ---------------------------------------------------------------------------
__device__ __forceinline__ u32 smem_u32(const void* p) {
    u32 a;
    asm("{ .reg .u64 t; cvta.to.shared.u64 t, %1; cvt.u32.u64 %0, t; }" : "=r"(a) : "l"(p));
    return a;
}
__device__ __forceinline__ void ldsm4(u32& r0, u32& r1, u32& r2, u32& r3, u32 a) {
    asm volatile("ldmatrix.sync.aligned.m8n8.x4.shared.b16 {%0,%1,%2,%3}, [%4];"
                 : "=r"(r0), "=r"(r1), "=r"(r2), "=r"(r3) : "r"(a));
}
__device__ __forceinline__ void ldsm4t(u32& r0, u32& r1, u32& r2, u32& r3, u32 a) {
    asm volatile("ldmatrix.sync.aligned.m8n8.x4.trans.shared.b16 {%0,%1,%2,%3}, [%4];"
                 : "=r"(r0), "=r"(r1), "=r"(r2), "=r"(r3) : "r"(a));
}
__device__ __forceinline__ void mma_f16(float* c, const u32* a, u32 b0, u32 b1) {
    asm volatile(
        "mma.sync.aligned.m16n8k16.row.col.f32.f16.f16.f32 "
        "{%0,%1,%2,%3}, {%4,%5,%6,%7}, {%8,%9}, {%0,%1,%2,%3};"
        : "+f"(c[0]), "+f"(c[1]), "+f"(c[2]), "+f"(c[3])
        : "r"(a[0]), "r"(a[1]), "r"(a[2]), "r"(a[3]), "r"(b0), "r"(b1));
}
__device__ __forceinline__ void cp16(u32 dst, const void* src) {
    asm volatile("cp.async.cg.shared.global [%0], [%1], 16;" :: "r"(dst), "l"(src));
}
#define CP_COMMIT() asm volatile("cp.async.commit_group;" ::: "memory")
#define CP_WAIT0()  asm volatile("cp.async.wait_group 0;" ::: "memory")
#define CP_WAIT1()  asm volatile("cp.async.wait_group 1;" ::: "memory")

__device__ __forceinline__ void split1(float v, __half& h, __half& l) {
    h = __float2half_rn(v);
    l = __float2half_rn(v - __half2float(h));
}

// ---------------------------------------------------------------------------
// fp32 -> fp16 convert
// ---------------------------------------------------------------------------
__global__ __launch_bounds__(256) void conv_kernel(const float* __restrict__ x,
                                                   __half* __restrict__ hi, int n) {
    const int i = (blockIdx.x * 256 + threadIdx.x) * 4;
    if (i >= n) return;
    float4 v = *(const float4*)(x + i);
    __half2 H0; H0.x = __float2half_rn(v.x); H0.y = __float2half_rn(v.y);
    __half2 H1; H1.x = __float2half_rn(v.z); H1.y = __float2half_rn(v.w);
    *(__half2*)(hi + i)     = H0;
    *(__half2*)(hi + i + 2) = H1;
}

// ---------------------------------------------------------------------------
// 1-pass GEMM: C = Ah @ Bh^T (+bias [+Qres])
// MODE 0: fp16 hi/lo (split of computed C) scattered to [B,H,S,DK]
// MODE 1: fp16 hi scattered to [B,H,S,DK]
// MODE 2: fp32 [M,N] + bias + Qres
// 128x128 tile, BK=32, cp.async double-buffered, 8 warps (warp tile 64x32)
// ---------------------------------------------------------------------------
#define GST    80                 // smem row stride bytes (40 fp16)
#define GMAT   (128 * GST)        // 10240
#define GSTAGE1 (2 * GMAT)        // [Ah][Bh]
#define GEMM1_SMEM (2 * GSTAGE1)  // 40960

template <int MODE>
__global__ __launch_bounds__(256) void gemm_mma1(
    const __half* __restrict__ Ahg, const __half* __restrict__ Bhg,
    const float* __restrict__ bias, const float* __restrict__ Qres,
    __half* __restrict__ o_hi, __half* __restrict__ o_lo,
    float* __restrict__ o_f) {
    extern __shared__ char smarr[];
    const u32 sb = smem_u32(smarr);
    const int tid = threadIdx.x, lane = tid & 31, wid = tid >> 5;
    const int wm = wid & 1, wn = wid >> 1;
    const int m0 = blockIdx.y * 128, n0 = blockIdx.x * 128;

    float acc[4][4][4];
#pragma unroll
    for (int a = 0; a < 4; ++a)
#pragma unroll
        for (int b = 0; b < 4; ++b)
#pragma unroll
            for (int c = 0; c < 4; ++c) acc[a][b][c] = 0.f;

    const __half* gsrc[2] = {Ahg + (size_t)m0 * DD, Bhg + (size_t)n0 * DD};

    auto LOAD = [&](int kt, int buf) {
        const int ko = kt * 32;
#pragma unroll
        for (int mat = 0; mat < 2; ++mat)
#pragma unroll
            for (int i = 0; i < 2; ++i) {
                const int ch = tid + i * 256;
                const int row = ch >> 2, c = ch & 3;
                cp16(sb + buf * GSTAGE1 + mat * GMAT + row * GST + c * 16,
                     gsrc[mat] + (size_t)row * DD + ko + c * 8);
            }
    };

    auto COMP = [&](int buf) {
        const u32 st = sb + buf * GSTAGE1;
#pragma unroll
        for (int s = 0; s < 2; ++s) {
            u32 ah[4][4];
#pragma unroll
            for (int mt = 0; mt < 4; ++mt) {
                const int row = wm * 64 + mt * 16 + (lane & 15);
                const int colb = (s * 16 + (lane >> 4) * 8) * 2;
                ldsm4(ah[mt][0], ah[mt][1], ah[mt][2], ah[mt][3], st + row * GST + colb);
            }
            u32 bh[2][4];
#pragma unroll
            for (int bt = 0; bt < 2; ++bt) {
                const int row = wn * 32 + bt * 16 + ((lane >> 4) & 1) * 8 + (lane & 7);
                const int colb = (s * 16 + ((lane >> 3) & 1) * 8) * 2;
                ldsm4(bh[bt][0], bh[bt][1], bh[bt][2], bh[bt][3],
                      st + GMAT + row * GST + colb);
            }
#pragma unroll
            for (int mt = 0; mt < 4; ++mt)
#pragma unroll
                for (int bt = 0; bt < 2; ++bt)
#pragma unroll
                    for (int j = 0; j < 2; ++j)
                        mma_f16(acc[mt][bt * 2 + j], ah[mt], bh[bt][2 * j], bh[bt][2 * j + 1]);
        }
    };

    LOAD(0, 0); CP_COMMIT();
    for (int kt = 0; kt < 32; ++kt) {
        const int buf = kt & 1;
        if (kt + 1 < 32) { LOAD(kt + 1, buf ^ 1); CP_COMMIT(); CP_WAIT1(); }
        else             { CP_WAIT0(); }
        __syncthreads();
        COMP(buf);
        __syncthreads();
    }

    const int r0 = lane >> 2, cp = (lane & 3) * 2;
#pragma unroll
    for (int mt = 0; mt < 4; ++mt)
#pragma unroll
        for (int i = 0; i < 2; ++i) {
            const int m = m0 + wm * 64 + mt * 16 + r0 + i * 8;
#pragma unroll
            for (int nt = 0; nt < 4; ++nt) {
                const int n = n0 + wn * 32 + nt * 8 + cp;
                float v0 = acc[mt][nt][i * 2 + 0] + __ldg(&bias[n]);
                float v1 = acc[mt][nt][i * 2 + 1] + __ldg(&bias[n + 1]);
                if (MODE == 0 || MODE == 1) {
                    const int bI = m >> 10, s = m & 1023;
                    const int h = n >> 6, d = n & 63;
                    const size_t o = ((size_t)(bI * HH + h) * SS + s) * DKK + d;
                    if (MODE == 0) {
                        __half h0, h1, l0, l1;
                        split1(v0, h0, l0); split1(v1, h1, l1);
                        __half2 hh; hh.x = h0; hh.y = h1;
                        __half2 ll; ll.x = l0; ll.y = l1;
                        *(__half2*)&o_hi[o] = hh;
                        *(__half2*)&o_lo[o] = ll;
                    } else {
                        __half2 hh;
                        hh.x = __float2half_rn(v0); hh.y = __float2half_rn(v1);
                        *(__half2*)&o_hi[o] = hh;
                    }
                } else {
                    const size_t o = (size_t)m * DD + n;
                    float2 qv = *(const float2*)&Qres[o];
                    float2 val; val.x = v0 + qv.x; val.y = v1 + qv.y;
                    *(float2*)&o_f[o] = val;
                }
            }
        }
}

// ---------------------------------------------------------------------------
// scores via mma.sync: per (b,h) 128x128 tile, K=64 single stage
//   S = qh@kh^T + ql@kh^T   (2-pass on computed-q split)
// ---------------------------------------------------------------------------
#define SSTR 144
#define SMAT (128 * SSTR)       // 18432
#define SC_SMEM (3 * SMAT)      // 55296

__global__ __launch_bounds__(256) void scores_mma(
    const __half* __restrict__ qh, const __half* __restrict__ ql,
    const __half* __restrict__ kh,
    const unsigned char* __restrict__ mask, float* __restrict__ scores) {
    extern __shared__ char smarr[];
    const u32 sb = smem_u32(smarr);
    const int tid = threadIdx.x, lane = tid & 31, wid = tid >> 5;
    const int wm = wid & 1, wn = wid >> 1;
    const int bh = blockIdx.z;
    const int m0 = blockIdx.y * 128, n0 = blockIdx.x * 128;

    const __half* gsrc[3] = {
        qh + ((size_t)bh * SS + m0) * DKK, ql + ((size_t)bh * SS + m0) * DKK,
        kh + ((size_t)bh * SS + n0) * DKK};
#pragma unroll
    for (int mat = 0; mat < 3; ++mat)
#pragma unroll
        for (int i = 0; i < 4; ++i) {
            const int ch = tid + i * 256;
            const int row = ch >> 3, c = ch & 7;
            cp16(sb + mat * SMAT + row * SSTR + c * 16,
                 gsrc[mat] + (size_t)row * DKK + c * 8);
        }
    CP_COMMIT(); CP_WAIT0();
    __syncthreads();

    float acc[4][4][4];
#pragma unroll
    for (int a = 0; a < 4; ++a)
#pragma unroll
        for (int b = 0; b < 4; ++b)
#pragma unroll
            for (int c = 0; c < 4; ++c) acc[a][b][c] = 0.f;

#pragma unroll
    for (int s = 0; s < 4; ++s) {
        u32 ah[4][4], al[4][4];
#pragma unroll
        for (int mt = 0; mt < 4; ++mt) {
            const int row = wm * 64 + mt * 16 + (lane & 15);
            const int colb = (s * 16 + (lane >> 4) * 8) * 2;
            const u32 ad = sb + row * SSTR + colb;
            ldsm4(ah[mt][0], ah[mt][1], ah[mt][2], ah[mt][3], ad);
            ldsm4(al[mt][0], al[mt][1], al[mt][2], al[mt][3], ad + SMAT);
        }
        u32 bh_[2][4];
#pragma unroll
        for (int bt = 0; bt < 2; ++bt) {
            const int row = wn * 32 + bt * 16 + ((lane >> 4) & 1) * 8 + (lane & 7);
            const int colb = (s * 16 + ((lane >> 3) & 1) * 8) * 2;
            ldsm4(bh_[bt][0], bh_[bt][1], bh_[bt][2], bh_[bt][3],
                  sb + 2 * SMAT + row * SSTR + colb);
        }
#pragma unroll
        for (int mt = 0; mt < 4; ++mt)
#pragma unroll
            for (int bt = 0; bt < 2; ++bt)
#pragma unroll
                for (int j = 0; j < 2; ++j) {
                    float* c = acc[mt][bt * 2 + j];
                    mma_f16(c, ah[mt], bh_[bt][2 * j], bh_[bt][2 * j + 1]);
                    mma_f16(c, al[mt], bh_[bt][2 * j], bh_[bt][2 * j + 1]);
                }
    }

    const int bI = bh >> 4;
    float* srow = scores + (size_t)bh * SS * SS;
    const unsigned char* mrow = mask + (size_t)bI * SS * SS;
    const int r0 = lane >> 2, cp = (lane & 3) * 2;
#pragma unroll
    for (int mt = 0; mt < 4; ++mt)
#pragma unroll
        for (int i = 0; i < 2; ++i) {
            const int m = m0 + wm * 64 + mt * 16 + r0 + i * 8;
#pragma unroll
            for (int nt = 0; nt < 4; ++nt) {
                const int n = n0 + wn * 32 + nt * 8 + cp;
                float v0 = acc[mt][nt][i * 2 + 0] * 0.125f;
                float v1 = acc[mt][nt][i * 2 + 1] * 0.125f;
                uchar2 mk = *(const uchar2*)&mrow[(size_t)m * SS + n];
                if (mk.x) v0 = -1e9f;
                if (mk.y) v1 = -1e9f;
                float2 val; val.x = v0; val.y = v1;
                *(float2*)&srow[(size_t)m * SS + n] = val;
            }
        }
}

// ---------------------------------------------------------------------------
// softmax: one WARP per 1024-float row; shfl-only reductions, MLP=8
// block = 256 threads = 8 rows; writes fp32 attn + fp16 hi
// ---------------------------------------------------------------------------
__global__ __launch_bounds__(256) void softmax_kernel(const float* __restrict__ scores,
                                                      float* __restrict__ attn,
                                                      __half* __restrict__ ahi) {
    const int w = threadIdx.x >> 5, lane = threadIdx.x & 31;
    const size_t row = (size_t)blockIdx.x * 8 + w;
    const float4* src = (const float4*)(scores + row * SS);

    float4 x[8];
#pragma unroll
    for (int i = 0; i < 8; ++i) x[i] = src[lane + 32 * i];

    float mx = -1e30f;
#pragma unroll
    for (int i = 0; i < 8; ++i)
        mx = fmaxf(mx, fmaxf(fmaxf(x[i].x, x[i].y), fmaxf(x[i].z, x[i].w)));
#pragma unroll
    for (int o = 16; o; o >>= 1) mx = fmaxf(mx, __shfl_xor_sync(0xffffffffu, mx, o));

    float s = 0.f;
#pragma unroll
    for (int i = 0; i < 8; ++i) {
        x[i].x = __expf(x[i].x - mx); x[i].y = __expf(x[i].y - mx);
        x[i].z = __expf(x[i].z - mx); x[i].w = __expf(x[i].w - mx);
        s += (x[i].x + x[i].y) + (x[i].z + x[i].w);
    }
#pragma unroll
    for (int o = 16; o; o >>= 1) s += __shfl_xor_sync(0xffffffffu, s, o);
    const float inv = 1.0f / s;

    float4* adst = (float4*)(attn + row * SS);
    __half* hdst = ahi + row * SS;
#pragma unroll
    for (int i = 0; i < 8; ++i) {
        float4 r;
        r.x = x[i].x * inv; r.y = x[i].y * inv;
        r.z = x[i].z * inv; r.w = x[i].w * inv;
        adst[lane + 32 * i] = r;
        __half2 H0; H0.x = __float2half_rn(r.x); H0.y = __float2half_rn(r.y);
        __half2 H1; H1.x = __float2half_rn(r.z); H1.y = __float2half_rn(r.w);
        const int c = (lane + 32 * i) * 4;
        *(__half2*)(hdst + c)     = H0;
        *(__half2*)(hdst + c + 2) = H1;
    }
}

// ---------------------------------------------------------------------------
// context (1-pass): ctx = attn_h @ Vh, writes ctx hi only
// ---------------------------------------------------------------------------
#define CAMAT  (128 * 80)                 // 10240
#define CVMAT  (32 * 144)                 // 4608
#define CSTAGE (CAMAT + CVMAT)            // 14848: [Ah][Vh]
#define CTX_SMEM (2 * CSTAGE)             // 29696

__global__ __launch_bounds__(256) void context_mma(
    const __half* __restrict__ ahg, const __half* __restrict__ vhg,
    __half* __restrict__ ctxh) {
    extern __shared__ char smarr[];
    const u32 sb = smem_u32(smarr);
    const int tid = threadIdx.x, lane = tid & 31, wid = tid >> 5;
    const int wm = wid >> 1, wn = wid & 1;
    const int bh = blockIdx.y;
    const int m0 = blockIdx.x * 128;

    const __half* asrc = ahg + ((size_t)bh * SS + m0) * SS;
    const __half* vsrc = vhg + (size_t)bh * SS * DKK;

    float acc[2][4][4];
#pragma unroll
    for (int a = 0; a < 2; ++a)
#pragma unroll
        for (int b = 0; b < 4; ++b)
#pragma unroll
            for (int c = 0; c < 4; ++c) acc[a][b][c] = 0.f;

    auto LOAD = [&](int kt, int buf) {
        const int ko = kt * 32;
#pragma unroll
        for (int i = 0; i < 2; ++i) {
            const int ch = tid + i * 256;
            const int row = ch >> 2, c = ch & 3;
            cp16(sb + buf * CSTAGE + row * 80 + c * 16,
                 asrc + (size_t)row * SS + ko + c * 8);
        }
        const int vr = tid >> 3, vc = tid & 7;
        cp16(sb + buf * CSTAGE + CAMAT + vr * 144 + vc * 16,
             vsrc + (size_t)(ko + vr) * DKK + vc * 8);
    };

    auto COMP = [&](int buf) {
        const u32 st = sb + buf * CSTAGE;
#pragma unroll
        for (int s = 0; s < 2; ++s) {
            u32 ah[2][4];
#pragma unroll
            for (int mt = 0; mt < 2; ++mt) {
                const int row = wm * 32 + mt * 16 + (lane & 15);
                const int colb = (s * 16 + (lane >> 4) * 8) * 2;
                ldsm4(ah[mt][0], ah[mt][1], ah[mt][2], ah[mt][3], st + row * 80 + colb);
            }
            u32 bh_[2][4];
#pragma unroll
            for (int bt = 0; bt < 2; ++bt) {
                const int rowk = s * 16 + (lane & 7) + ((lane >> 3) & 1) * 8;
                const int coln = wn * 32 + bt * 16 + ((lane >> 4) & 1) * 8;
                ldsm4t(bh_[bt][0], bh_[bt][1], bh_[bt][2], bh_[bt][3],
                       st + CAMAT + rowk * 144 + coln * 2);
            }
#pragma unroll
            for (int mt = 0; mt < 2; ++mt)
#pragma unroll
                for (int bt = 0; bt < 2; ++bt)
#pragma unroll
                    for (int j = 0; j < 2; ++j)
                        mma_f16(acc[mt][bt * 2 + j], ah[mt], bh_[bt][2 * j], bh_[bt][2 * j + 1]);
        }
    };

    LOAD(0, 0); CP_COMMIT();
    for (int kt = 0; kt < 32; ++kt) {
        const int buf = kt & 1;
        if (kt + 1 < 32) { LOAD(kt + 1, buf ^ 1); CP_COMMIT(); CP_WAIT1(); }
        else             { CP_WAIT0(); }
        __syncthreads();
        COMP(buf);
        __syncthreads();
    }

    const int bI = bh >> 4, h = bh & 15;
    const int r0 = lane >> 2, cp = (lane & 3) * 2;
#pragma unroll
    for (int mt = 0; mt < 2; ++mt)
#pragma unroll
        for (int i = 0; i < 2; ++i) {
            const int m = m0 + wm * 32 + mt * 16 + r0 + i * 8;
#pragma unroll
            for (int nt = 0; nt < 4; ++nt) {
                const int n = wn * 32 + nt * 8 + cp;
                __half2 hh;
                hh.x = __float2half_rn(acc[mt][nt][i * 2 + 0]);
                hh.y = __float2half_rn(acc[mt][nt][i * 2 + 1]);
                const size_t o = ((size_t)bI * SS + m) * DD + h * DKK + n;
                *(__half2*)&ctxh[o] = hh;
            }
        }
}

// ---------------------------------------------------------------------------
// launch
// ---------------------------------------------------------------------------
extern "C" void kernel_launch(void* const* d_in, const int* in_sizes, int n_in,
                              void* d_out, int out_size) {
    const float* Q  = (const float*)d_in[0];
    const float* K  = (const float*)d_in[1];
    const float* V  = (const float*)d_in[2];
    const unsigned char* mask = (const unsigned char*)d_in[3];
    const float* Wq = (const float*)d_in[4];
    const float* bq = (const float*)d_in[5];
    const float* Wk = (const float*)d_in[6];
    const float* bk = (const float*)d_in[7];
    const float* Wv = (const float*)d_in[8];
    const float* bv = (const float*)d_in[9];
    const float* Wo = (const float*)d_in[10];
    const float* bo = (const float*)d_in[11];

    float* out    = (float*)d_out;
    float* attn   = out + (size_t)BB * SS * DD;
    float* scores = attn + (size_t)BB * HH * SS * SS;

    __half *pQih, *pKih, *pVih;
    __half *pWqh, *pWkh, *pWvh, *pWoh;
    __half *pqh, *pql, *pkh, *pvh, *pah, *pctxh;
    cudaGetSymbolAddress((void**)&pQih, gQih);
    cudaGetSymbolAddress((void**)&pKih, gKih);
    cudaGetSymbolAddress((void**)&pVih, gVih);
    cudaGetSymbolAddress((void**)&pWqh, gWqh); cudaGetSymbolAddress((void**)&pWkh, gWkh);
    cudaGetSymbolAddress((void**)&pWvh, gWvh); cudaGetSymbolAddress((void**)&pWoh, gWoh);
    cudaGetSymbolAddress((void**)&pqh, gqh);   cudaGetSymbolAddress((void**)&pql, gql);
    cudaGetSymbolAddress((void**)&pkh, gkh);   cudaGetSymbolAddress((void**)&pvh, gvh);
    cudaGetSymbolAddress((void**)&pah, gattnh);
    cudaGetSymbolAddress((void**)&pctxh, gctxh);

    static int initd = 0;
    if (!initd) {
        cudaFuncSetAttribute(gemm_mma1<0>, cudaFuncAttributeMaxDynamicSharedMemorySize, GEMM1_SMEM);
        cudaFuncSetAttribute(gemm_mma1<1>, cudaFuncAttributeMaxDynamicSharedMemorySize, GEMM1_SMEM);
        cudaFuncSetAttribute(gemm_mma1<2>, cudaFuncAttributeMaxDynamicSharedMemorySize, GEMM1_SMEM);
        cudaFuncSetAttribute(scores_mma, cudaFuncAttributeMaxDynamicSharedMemorySize, SC_SMEM);
        cudaFuncSetAttribute(context_mma, cudaFuncAttributeMaxDynamicSharedMemorySize, CTX_SMEM);
        initd = 1;
    }

    conv_kernel<<<NEL / 1024, 256>>>(Q, pQih, NEL);
    conv_kernel<<<NEL / 1024, 256>>>(K, pKih, NEL);
    conv_kernel<<<NEL / 1024, 256>>>(V, pVih, NEL);
    conv_kernel<<<WEL / 1024, 256>>>(Wq, pWqh, WEL);
    conv_kernel<<<WEL / 1024, 256>>>(Wk, pWkh, WEL);
    conv_kernel<<<WEL / 1024, 256>>>(Wv, pWvh, WEL);
    conv_kernel<<<WEL / 1024, 256>>>(Wo, pWoh, WEL);

    const dim3 gemmGrid(DD / 128, MTOT / 128);          // (8, 64)
    gemm_mma1<0><<<gemmGrid, 256, GEMM1_SMEM>>>(pQih, pWqh, bq, nullptr, pqh, pql, nullptr);
    gemm_mma1<1><<<gemmGrid, 256, GEMM1_SMEM>>>(pKih, pWkh, bk, nullptr, pkh, nullptr, nullptr);
    gemm_mma1<1><<<gemmGrid, 256, GEMM1_SMEM>>>(pVih, pWvh, bv, nullptr, pvh, nullptr, nullptr);

    const dim3 scoreGrid(SS / 128, SS / 128, BB * HH);  // (8, 8, 128)
    scores_mma<<<scoreGrid, 256, SC_SMEM>>>(pqh, pql, pkh, mask, scores);

    softmax_kernel<<<BB * HH * SS / 8, 256>>>(scores, attn, pah);

    const dim3 ctxGrid(SS / 128, BB * HH);              // (8, 128)
    context_mma<<<ctxGrid, 256, CTX_SMEM>>>(pah, pvh, pctxh);

    gemm_mma1<2><<<gemmGrid, 256, GEMM1_SMEM>>>(pctxh, pWoh, bo, Q, nullptr, nullptr, out);
}